// round 15
// baseline (speedup 1.0000x reference)
#include <cuda_runtime.h>
#include <cuda_fp16.h>
#include <math.h>
#include <stdint.h>

// ---------------------------------------------------------------------------
// TernaryCIFAR10Net forward, B=1024 — fp16 mma.sync; bulk-copy staging;
// 256-thread conv CTAs (2/SM). conv3 CTAs cover 2 images x 128 oc so each
// weight stage is amortized over 2x the MMAs (halves weight staging traffic).
// ---------------------------------------------------------------------------

#define NB 1024
typedef unsigned long long u64;
typedef __half h16;

__device__ __forceinline__ uint32_t smem_u32(const void* p) {
    uint32_t a;
    asm("{ .reg .u64 t; cvta.to.shared.u64 t, %1; cvt.u32.u64 %0, t; }" : "=r"(a) : "l"(p));
    return a;
}
__device__ __forceinline__ void ldsm4(uint32_t addr, uint32_t& r0, uint32_t& r1,
                                      uint32_t& r2, uint32_t& r3) {
    asm volatile("ldmatrix.sync.aligned.m8n8.x4.shared.b16 {%0,%1,%2,%3}, [%4];"
                 : "=r"(r0), "=r"(r1), "=r"(r2), "=r"(r3) : "r"(addr));
}
__device__ __forceinline__ void mmaf16(float* d, uint32_t a0, uint32_t a1, uint32_t a2,
                                       uint32_t a3, uint32_t b0, uint32_t b1) {
    asm volatile("mma.sync.aligned.m16n8k16.row.col.f32.f16.f16.f32 "
                 "{%0,%1,%2,%3}, {%4,%5,%6,%7}, {%8,%9}, {%0,%1,%2,%3};"
                 : "+f"(d[0]), "+f"(d[1]), "+f"(d[2]), "+f"(d[3])
                 : "r"(a0), "r"(a1), "r"(a2), "r"(a3), "r"(b0), "r"(b1));
}
#define MBAR_INIT(mbar, count) \
    asm volatile("mbarrier.init.shared.b64 [%0], %1;" :: "r"((uint32_t)(mbar)), "r"((uint32_t)(count)) : "memory")
#define MBAR_EXPECT(mbar, bytes) \
    asm volatile("mbarrier.arrive.expect_tx.shared.b64 _, [%0], %1;" \
                 :: "r"((uint32_t)(mbar)), "r"((uint32_t)(bytes)) : "memory")
#define MBAR_WAIT(mbar, parity) do {                                                         \
    uint32_t _m = (uint32_t)(mbar); uint32_t _p = (uint32_t)(parity); uint32_t _done;        \
    asm volatile("{\n\t.reg .pred p;\n\t"                                                    \
        "mbarrier.try_wait.parity.acquire.cta.shared::cta.b64 p, [%1], %2;\n\t"              \
        "selp.b32 %0, 1, 0, p;\n\t}" : "=r"(_done) : "r"(_m), "r"(_p) : "memory");           \
    if (!_done) {                                                                            \
        asm volatile("{\n\t.reg .pred P1;\n\t"                                               \
            "WAIT_LOOP_%=:\n\t"                                                              \
            "mbarrier.try_wait.parity.acquire.cta.shared::cta.b64 P1, [%0], %1, 0x989680;\n\t" \
            "@P1 bra.uni WAIT_DONE_%=;\n\t"                                                  \
            "bra.uni WAIT_LOOP_%=;\n\t"                                                      \
            "WAIT_DONE_%=:\n\t}" :: "r"(_m), "r"(_p) : "memory");                            \
    }                                                                                        \
} while (0)
#define BULK_LD(dst, src, bytes, mbar) \
    asm volatile("{\n\t.reg .u64 g;\n\tcvta.to.global.u64 g, %1;\n\t" \
        "cp.async.bulk.shared::cluster.global.mbarrier::complete_tx::bytes [%0], [g], %2, [%3];\n\t}" \
        :: "r"((uint32_t)(dst)), "l"(src), "r"((uint32_t)(bytes)), "r"((uint32_t)(mbar)) : "memory")

// ========================= device scratch ===================================
#define A1R 23360
#define A2R 13632
__device__ __align__(16) h16 g_a1[NB * A1R];
__device__ __align__(16) h16 g_a2[NB * A2R];
__device__ __align__(16) h16 g_act3[NB * 16 * 256]; // [n][s][c]
__device__ float g_fc1p[8 * NB * 256];

__device__ __align__(16) h16 g_w1s[64 * 72];           // [oc][k pad72]
__device__ __align__(16) h16 g_w2s[9 * 128 * 72];      // [tap][oc][ic pad72]
__device__ __align__(16) h16 g_w3s[9 * 2 * 256 * 72];  // [tap][ichalf][oc][ic64 pad72]
__device__ __align__(16) h16 g_wf1s[256 * 4096];       // [o][k'], k'=s*256+c
__device__ float g_wf2t[10 * 256];

__device__ float g_p1[5][128];
__device__ int   g_c1[5];
__device__ float g_p2s[5][256];
__device__ float g_p2c[5][256];
__device__ int   g_c2[5];
__device__ float g_delta[5];
__device__ float g_alpha[5];

__constant__ int c_n[5] = {64 * 3 * 9, 128 * 64 * 9, 256 * 128 * 9, 256 * 4096, 10 * 256};

__device__ __forceinline__ const float* pick_src(int t, const float* a, const float* b,
                                                 const float* c, const float* d, const float* e) {
    switch (t) { case 0: return a; case 1: return b; case 2: return c; case 3: return d; default: return e; }
}

// ========================= ternarization (2 kernels) ========================
__global__ void k_tern1(const float* __restrict__ a, const float* __restrict__ b,
                        const float* __restrict__ c, const float* __restrict__ d,
                        const float* __restrict__ e) {
    int t = blockIdx.y, tid = threadIdx.x;
    const float* w = pick_src(t, a, b, c, d, e);
    int n = c_n[t];
    float s = 0.f;
    for (int i = blockIdx.x * 256 + tid; i < n; i += 128 * 256) s += fabsf(w[i]);
    __shared__ float sm[256];
    __shared__ int slast;
    sm[tid] = s; __syncthreads();
    for (int st = 128; st > 0; st >>= 1) {
        if (tid < st) sm[tid] += sm[tid + st];
        __syncthreads();
    }
    if (tid == 0) {
        g_p1[t][blockIdx.x] = sm[0];
        __threadfence();
        int old = atomicAdd(&g_c1[t], 1);
        slast = (old == 127) ? 1 : 0;
    }
    __syncthreads();
    if (slast) {
        __shared__ float r[128];
        if (tid < 128) r[tid] = g_p1[t][tid];
        __syncthreads();
        for (int st = 64; st > 0; st >>= 1) {
            if (tid < st) r[tid] += r[tid + st];
            __syncthreads();
        }
        if (tid == 0) { g_delta[t] = 0.7f * r[0] / (float)n; g_c1[t] = 0; }
    }
}

__global__ void k_tern2(const float* __restrict__ a, const float* __restrict__ b,
                        const float* __restrict__ c, const float* __restrict__ d,
                        const float* __restrict__ e) {
    int t = blockIdx.y, tid = threadIdx.x;
    const float* w = pick_src(t, a, b, c, d, e);
    int n = c_n[t];
    float dlt = g_delta[t];
    float s = 0.f, cn = 0.f;
    for (int i = blockIdx.x * 256 + tid; i < n; i += 256 * 256) {
        float v = w[i];
        float av = fabsf(v);
        float sg;
        if (av > dlt) { s += av; cn += 1.f; sg = (v > 0.f ? 1.f : -1.f); } else sg = 0.f;
        switch (t) {
            case 0: { int oc = i / 27,   r = i % 27;  g_w1s[oc * 72 + r] = __float2half(sg); } break;
            case 1: { int oc = i / 576,  r = i % 576;  int ic = r / 9, k = r % 9;
                      g_w2s[(k * 128 + oc) * 72 + ic] = __float2half(sg); } break;
            case 2: { int oc = i / 1152, r = i % 1152; int ic = r / 9, k = r % 9;
                      g_w3s[((k * 2 + (ic >> 6)) * 256 + oc) * 72 + (ic & 63)] = __float2half(sg); } break;
            case 3: { int o = i >> 12, k = i & 4095; int ch = k >> 4, s4 = k & 15;
                      g_wf1s[o * 4096 + s4 * 256 + ch] = __float2half(sg); } break;
            default: g_wf2t[i] = sg;
        }
    }
    __shared__ float sm[256], sc[256];
    __shared__ int slast;
    sm[tid] = s; sc[tid] = cn; __syncthreads();
    for (int st = 128; st > 0; st >>= 1) {
        if (tid < st) { sm[tid] += sm[tid + st]; sc[tid] += sc[tid + st]; }
        __syncthreads();
    }
    if (tid == 0) {
        g_p2s[t][blockIdx.x] = sm[0];
        g_p2c[t][blockIdx.x] = sc[0];
        __threadfence();
        int old = atomicAdd(&g_c2[t], 1);
        slast = (old == 255) ? 1 : 0;
    }
    __syncthreads();
    if (slast) {
        sm[tid] = g_p2s[t][tid];
        sc[tid] = g_p2c[t][tid];
        __syncthreads();
        for (int st = 128; st > 0; st >>= 1) {
            if (tid < st) { sm[tid] += sm[tid + st]; sc[tid] += sc[tid + st]; }
            __syncthreads();
        }
        if (tid == 0) { g_alpha[t] = sm[0] / fmaxf(sc[0], 1.f); g_c2[t] = 0; }
    }
}

// ========================= conv1: 3->64 (tensor, im2col) ====================
#define C1_SIN 0
#define C1_A 4096
#define C1_B 40960
#define C1_BIAS 50176
#define C1_SMEM 50448
__global__ __launch_bounds__(256, 2) void k_conv1t(const float* __restrict__ x,
                                                   const float* __restrict__ b1) {
    extern __shared__ __align__(128) char smem[];
    uint32_t sbase = smem_u32(smem);
    int tid = threadIdx.x, wid = tid >> 5, lane = tid & 31;
    int n = blockIdx.x >> 2, q = blockIdx.x & 3;
    float* sinp = (float*)(smem + C1_SIN);
    float* sbias = (float*)(smem + C1_BIAS);
    if (tid < 64) sbias[tid] = b1[tid];

    for (int i = tid; i < 1020; i += 256) {
        int c = i / 340, r = i - c * 340, yy = r / 34, xx = r - yy * 34;
        int gy = q * 8 + yy - 1, gx = xx - 1;
        float v = 0.f;
        if (gy >= 0 && gy < 32 && gx >= 0 && gx < 32)
            v = x[((n * 3 + c) * 32 + gy) * 32 + gx];
        sinp[i] = v;
    }
    for (int i = tid; i < 576; i += 256)
        *(uint4*)(smem + C1_B + i * 16) = ((const uint4*)g_w1s)[i];
    __syncthreads();

    {
        int b = tid >> 2, c = tid & 3;
        int by = b >> 4, bx = b & 15;
        int y0 = by * 2 + (c >> 1), x0 = bx * 2 + (c & 1);
        unsigned short hh[32];
#pragma unroll
        for (int k = 0; k < 27; k++) {
            int ch = k / 9, r = k - ch * 9, ky = r / 3, kx = r - ky * 3;
            hh[k] = __half_as_ushort(__float2half(sinp[(ch * 10 + y0 + ky) * 34 + x0 + kx]));
        }
#pragma unroll
        for (int k = 27; k < 32; k++) hh[k] = 0;
        char* dst = smem + C1_A + tid * 144;
#pragma unroll
        for (int j = 0; j < 4; j++) *(uint4*)(dst + j * 16) = *(uint4*)&hh[j * 8];
    }
    __syncthreads();

    float alpha = g_alpha[0];
    uint32_t khalf16 = (uint32_t)((lane >> 4) << 4);
    uint32_t bRowOff = sbase + C1_B + (uint32_t)(lane & 15) * 144 + khalf16;
    uint32_t bf[2][4][4];
#pragma unroll
    for (int kc = 0; kc < 2; kc++)
#pragma unroll
        for (int nt2 = 0; nt2 < 4; nt2++)
            ldsm4(bRowOff + kc * 32 + nt2 * 2304,
                  bf[kc][nt2][0], bf[kc][nt2][1], bf[kc][nt2][2], bf[kc][nt2][3]);

    int t2 = lane & 3;
    bool wr = (lane & 12) == 0;
#pragma unroll
    for (int h = 0; h < 2; h++) {
        int mt = wid + 8 * h;
        uint32_t aAddr = sbase + C1_A + (uint32_t)(mt * 16 + (lane & 15)) * 144 + khalf16;
        float acc[8][4];
#pragma unroll
        for (int i = 0; i < 8; i++)
#pragma unroll
            for (int j = 0; j < 4; j++) acc[i][j] = 0.f;
#pragma unroll
        for (int kc = 0; kc < 2; kc++) {
            uint32_t a0, a1, a2, a3;
            ldsm4(aAddr + kc * 32, a0, a1, a2, a3);
#pragma unroll
            for (int nt2 = 0; nt2 < 4; nt2++) {
                mmaf16(acc[2 * nt2],     a0, a1, a2, a3, bf[kc][nt2][0], bf[kc][nt2][2]);
                mmaf16(acc[2 * nt2 + 1], a0, a1, a2, a3, bf[kc][nt2][1], bf[kc][nt2][3]);
            }
        }
        int blk0 = mt * 4 + (lane >> 4);
#pragma unroll
        for (int nt = 0; nt < 8; nt++) {
            float v0 = acc[nt][0], v1 = acc[nt][1], v2 = acc[nt][2], v3 = acc[nt][3];
            v0 = fmaxf(v0, __shfl_xor_sync(0xffffffffu, v0, 4));
            v0 = fmaxf(v0, __shfl_xor_sync(0xffffffffu, v0, 8));
            v1 = fmaxf(v1, __shfl_xor_sync(0xffffffffu, v1, 4));
            v1 = fmaxf(v1, __shfl_xor_sync(0xffffffffu, v1, 8));
            v2 = fmaxf(v2, __shfl_xor_sync(0xffffffffu, v2, 4));
            v2 = fmaxf(v2, __shfl_xor_sync(0xffffffffu, v2, 8));
            v3 = fmaxf(v3, __shfl_xor_sync(0xffffffffu, v3, 4));
            v3 = fmaxf(v3, __shfl_xor_sync(0xffffffffu, v3, 8));
            if (wr) {
                int oc = nt * 8 + t2 * 2;
                float bi0 = sbias[oc], bi1 = sbias[oc + 1];
#pragma unroll
                for (int p = 0; p < 2; p++) {
                    int blk = blk0 + p * 2;
                    float w0 = fmaxf(alpha * (p ? v2 : v0) + bi0, 0.f);
                    float w1 = fmaxf(alpha * (p ? v3 : v1) + bi1, 0.f);
                    int py = q * 4 + (blk >> 4), px = blk & 15;
                    int pl = (py + 1) * 18 + (px + 1);
                    ushort2 st;
                    st.x = __half_as_ushort(__float2half(w0));
                    st.y = __half_as_ushort(__float2half(w1));
                    *(ushort2*)((unsigned short*)g_a1 + n * A1R + pl * 72 +
                                (((py + 1) & 1) << 4) + oc) = st;
                }
            }
        }
    }
}

// ========================= conv2: 64->128 (256 thr, half image, 2 CTA/SM) ===
#define C2_HALO 0
#define C2_B0 25984
#define C2_BSZ 18432
#define C2_BIAS (C2_B0 + 4 * C2_BSZ)
#define C2_MBAR (C2_BIAS + 512)
#define C2_SMEM (C2_MBAR + 48)
__global__ __launch_bounds__(256, 2) void k_conv2f(const float* __restrict__ b2) {
    extern __shared__ __align__(128) char smem[];
    uint32_t sb = smem_u32(smem);
    int tid = threadIdx.x, wid = tid >> 5, lane = tid & 31;
    int wm = wid & 3, wn = wid >> 2;
    int n = blockIdx.x >> 1, hf = blockIdx.x & 1;
    float* sbias = (float*)(smem + C2_BIAS);
    if (tid < 128) sbias[tid] = b2[tid];

    if (tid == 0) {
#pragma unroll
        for (int i = 0; i < 5; i++) MBAR_INIT(sb + C2_MBAR + i * 8, 1);
    }
    __syncthreads();
    if (tid == 0) {
        MBAR_EXPECT(sb + C2_MBAR + 32, 25952);
        BULK_LD(sb + C2_HALO, (const char*)g_a1 + (size_t)n * 46720 + hf * 20736,
                25952, sb + C2_MBAR + 32);
        MBAR_EXPECT(sb + C2_MBAR + 0, C2_BSZ);
        BULK_LD(sb + C2_B0, (const char*)g_w2s, C2_BSZ, sb + C2_MBAR + 0);
        MBAR_EXPECT(sb + C2_MBAR + 8, C2_BSZ);
        BULK_LD(sb + C2_B0 + C2_BSZ, (const char*)g_w2s + C2_BSZ, C2_BSZ, sb + C2_MBAR + 8);
    }

    int y_m[2], x_m[2];
#pragma unroll
    for (int h = 0; h < 2; h++) {
        int m = (wm + 4 * h) * 16 + (lane & 15);
        int b = m >> 2, c = m & 3;
        y_m[h] = ((b >> 3) << 1) + (c >> 1);
        x_m[h] = ((b & 7) << 1) + (c & 1);
    }
    uint32_t khalf16 = (uint32_t)((lane >> 4) << 4);
    uint32_t bRowOff = (uint32_t)(wn * 64 + (lane & 15)) * 144 + khalf16;

    float acc[2][8][4];
#pragma unroll
    for (int h = 0; h < 2; h++)
#pragma unroll
        for (int i = 0; i < 8; i++)
#pragma unroll
            for (int j = 0; j < 4; j++) acc[h][i][j] = 0.f;

    MBAR_WAIT(sb + C2_MBAR + 32, 0);

    for (int tap = 0; tap < 9; tap++) {
        if (tid == 0 && tap + 2 < 9) {
            int nx = tap + 2;
            MBAR_EXPECT(sb + C2_MBAR + (nx & 3) * 8, C2_BSZ);
            BULK_LD(sb + C2_B0 + (nx & 3) * C2_BSZ, (const char*)g_w2s + nx * C2_BSZ,
                    C2_BSZ, sb + C2_MBAR + (nx & 3) * 8);
        }
        MBAR_WAIT(sb + C2_MBAR + (tap & 3) * 8, (tap >> 2) & 1);

        int ky = tap / 3, kx = tap - ky * 3;
        uint32_t aA[2];
#pragma unroll
        for (int h = 0; h < 2; h++) {
            int hy = y_m[h] + ky;
            aA[h] = sb + C2_HALO + (uint32_t)(hy * 18 + x_m[h] + kx) * 144 +
                    (uint32_t)((hy & 1) << 5) + khalf16;
        }
        uint32_t bBuf = sb + C2_B0 + (uint32_t)((tap & 3) * C2_BSZ);
#pragma unroll
        for (int kc = 0; kc < 4; kc++) {
            uint32_t a00, a01, a02, a03, a10, a11, a12, a13;
            ldsm4(aA[0] + kc * 32, a00, a01, a02, a03);
            ldsm4(aA[1] + kc * 32, a10, a11, a12, a13);
#pragma unroll
            for (int nt2 = 0; nt2 < 4; nt2++) {
                uint32_t r0, r1, r2, r3;
                ldsm4(bBuf + bRowOff + nt2 * 2304 + kc * 32, r0, r1, r2, r3);
                mmaf16(acc[0][2 * nt2],     a00, a01, a02, a03, r0, r2);
                mmaf16(acc[0][2 * nt2 + 1], a00, a01, a02, a03, r1, r3);
                mmaf16(acc[1][2 * nt2],     a10, a11, a12, a13, r0, r2);
                mmaf16(acc[1][2 * nt2 + 1], a10, a11, a12, a13, r1, r3);
            }
        }
        __syncthreads();
    }

    float alpha = g_alpha[1];
    int t2 = lane & 3;
    bool wr = (lane & 12) == 0;
#pragma unroll
    for (int h = 0; h < 2; h++) {
        int mt = hf * 8 + wm + 4 * h;
        int blk0 = mt * 4 + (lane >> 4);
#pragma unroll
        for (int nt = 0; nt < 8; nt++) {
            float v0 = acc[h][nt][0], v1 = acc[h][nt][1], v2 = acc[h][nt][2], v3 = acc[h][nt][3];
            v0 = fmaxf(v0, __shfl_xor_sync(0xffffffffu, v0, 4));
            v0 = fmaxf(v0, __shfl_xor_sync(0xffffffffu, v0, 8));
            v1 = fmaxf(v1, __shfl_xor_sync(0xffffffffu, v1, 4));
            v1 = fmaxf(v1, __shfl_xor_sync(0xffffffffu, v1, 8));
            v2 = fmaxf(v2, __shfl_xor_sync(0xffffffffu, v2, 4));
            v2 = fmaxf(v2, __shfl_xor_sync(0xffffffffu, v2, 8));
            v3 = fmaxf(v3, __shfl_xor_sync(0xffffffffu, v3, 4));
            v3 = fmaxf(v3, __shfl_xor_sync(0xffffffffu, v3, 8));
            if (wr) {
                int oc = wn * 64 + nt * 8 + t2 * 2;
                float bi0 = sbias[oc], bi1 = sbias[oc + 1];
#pragma unroll
                for (int p = 0; p < 2; p++) {
                    int blk = blk0 + p * 2;
                    float w0 = fmaxf(alpha * (p ? v2 : v0) + bi0, 0.f);
                    float w1 = fmaxf(alpha * (p ? v3 : v1) + bi1, 0.f);
                    int py = blk >> 3, px = blk & 7;
                    int pl = (py + 1) * 10 + (px + 1);
                    ushort2 st;
                    st.x = __half_as_ushort(__float2half(w0));
                    st.y = __half_as_ushort(__float2half(w1));
                    *(ushort2*)((unsigned short*)g_a2 + n * A2R + pl * 136 +
                                (((py + 1) & 1) << 4) + oc) = st;
                }
            }
        }
    }
}

// ========================= conv3: 2 images x 128 oc per CTA ================
// grid 1024 = 512 image-pairs x 2 oc-halves; 256 thr, 8 warps = 4m x 2n.
#define C3_HALO 0
#define C3_B0 54528
#define C3_BSZ 18432
#define C3_BIAS (C3_B0 + 2 * C3_BSZ)
#define C3_MBAR (C3_BIAS + 1024)
#define C3_SMEM (C3_MBAR + 32)
__global__ __launch_bounds__(256, 2) void k_conv3f(const float* __restrict__ b3) {
    extern __shared__ __align__(128) char smem[];
    uint32_t sb = smem_u32(smem);
    int tid = threadIdx.x, wid = tid >> 5, lane = tid & 31;
    int wm = wid & 3, wn = wid >> 2;           // 4 m-warps x 2 n-warps
    int pr = blockIdx.x >> 1, oh = blockIdx.x & 1;
    int n0 = pr * 2;
    float* sbias = (float*)(smem + C3_BIAS);
    sbias[tid] = b3[tid];

    if (tid == 0) {
#pragma unroll
        for (int i = 0; i < 3; i++) MBAR_INIT(sb + C3_MBAR + i * 8, 1);
    }
    __syncthreads();
    if (tid == 0) {
        MBAR_EXPECT(sb + C3_MBAR + 16, 2 * 27264);
        BULK_LD(sb + C3_HALO,         (const char*)g_a2 + (size_t)n0 * 27264,       27264, sb + C3_MBAR + 16);
        BULK_LD(sb + C3_HALO + 27264, (const char*)g_a2 + (size_t)(n0 + 1) * 27264, 27264, sb + C3_MBAR + 16);
        MBAR_EXPECT(sb + C3_MBAR + 0, C3_BSZ);
        BULK_LD(sb + C3_B0, (const char*)g_w3s + (size_t)(oh * 128) * 144, C3_BSZ, sb + C3_MBAR + 0);
    }

    int y_m[2], x_m[2], img_m[2];
#pragma unroll
    for (int h = 0; h < 2; h++) {
        int m = (wm + 4 * h) * 16 + (lane & 15);   // 0..127
        img_m[h] = m >> 6;
        int r = m & 63;
        int bl = r >> 2, c = r & 3;
        y_m[h] = ((bl >> 2) << 1) + (c >> 1);
        x_m[h] = ((bl & 3) << 1) + (c & 1);
    }
    uint32_t khalf16 = (uint32_t)((lane >> 4) << 4);
    uint32_t bRowOff = (uint32_t)(wn * 64 + (lane & 15)) * 144 + khalf16;

    float acc[2][8][4];
#pragma unroll
    for (int h = 0; h < 2; h++)
#pragma unroll
        for (int i = 0; i < 8; i++)
#pragma unroll
            for (int j = 0; j < 4; j++) acc[h][i][j] = 0.f;

    MBAR_WAIT(sb + C3_MBAR + 16, 0);   // halos ready

    for (int st = 0; st < 18; st++) {
        if (tid == 0 && st + 1 < 18) {
            int nx = st + 1;
            MBAR_EXPECT(sb + C3_MBAR + (nx & 1) * 8, C3_BSZ);
            BULK_LD(sb + C3_B0 + (nx & 1) * C3_BSZ,
                    (const char*)g_w3s + (size_t)(nx * 256 + oh * 128) * 144,
                    C3_BSZ, sb + C3_MBAR + (nx & 1) * 8);
        }
        MBAR_WAIT(sb + C3_MBAR + (st & 1) * 8, (st >> 1) & 1);

        int tap = st >> 1, chalf = (st & 1) * 128;
        int ky = tap / 3, kx = tap - ky * 3;
        uint32_t aA[2];
#pragma unroll
        for (int h = 0; h < 2; h++) {
            int hy = y_m[h] + ky;
            aA[h] = sb + C3_HALO + (uint32_t)(img_m[h] * 27264) +
                    (uint32_t)(hy * 10 + x_m[h] + kx) * 272 +
                    (uint32_t)((hy & 1) << 5) + (uint32_t)chalf + khalf16;
        }
        uint32_t bBuf = sb + C3_B0 + (uint32_t)((st & 1) * C3_BSZ);
#pragma unroll
        for (int kc = 0; kc < 4; kc++) {
            uint32_t a00, a01, a02, a03, a10, a11, a12, a13;
            ldsm4(aA[0] + kc * 32, a00, a01, a02, a03);
            ldsm4(aA[1] + kc * 32, a10, a11, a12, a13);
#pragma unroll
            for (int nt2 = 0; nt2 < 4; nt2++) {
                uint32_t r0, r1, r2, r3;
                ldsm4(bBuf + bRowOff + nt2 * 2304 + kc * 32, r0, r1, r2, r3);
                mmaf16(acc[0][2 * nt2],     a00, a01, a02, a03, r0, r2);
                mmaf16(acc[0][2 * nt2 + 1], a00, a01, a02, a03, r1, r3);
                mmaf16(acc[1][2 * nt2],     a10, a11, a12, a13, r0, r2);
                mmaf16(acc[1][2 * nt2 + 1], a10, a11, a12, a13, r1, r3);
            }
        }
        __syncthreads();
    }

    float alpha = g_alpha[2];
    int t2 = lane & 3;
    bool wr = (lane & 12) == 0;
#pragma unroll
    for (int h = 0; h < 2; h++) {
        int mt = wm + 4 * h;                   // 0..7
        int img = n0 + (mt >> 2);
        int blk0 = (mt & 3) * 4 + (lane >> 4);
#pragma unroll
        for (int nt = 0; nt < 8; nt++) {
            float v0 = acc[h][nt][0], v1 = acc[h][nt][1], v2 = acc[h][nt][2], v3 = acc[h][nt][3];
            v0 = fmaxf(v0, __shfl_xor_sync(0xffffffffu, v0, 4));
            v0 = fmaxf(v0, __shfl_xor_sync(0xffffffffu, v0, 8));
            v1 = fmaxf(v1, __shfl_xor_sync(0xffffffffu, v1, 4));
            v1 = fmaxf(v1, __shfl_xor_sync(0xffffffffu, v1, 8));
            v2 = fmaxf(v2, __shfl_xor_sync(0xffffffffu, v2, 4));
            v2 = fmaxf(v2, __shfl_xor_sync(0xffffffffu, v2, 8));
            v3 = fmaxf(v3, __shfl_xor_sync(0xffffffffu, v3, 4));
            v3 = fmaxf(v3, __shfl_xor_sync(0xffffffffu, v3, 8));
            if (wr) {
                int oc = oh * 128 + wn * 64 + nt * 8 + t2 * 2;
                float bi0 = sbias[oc], bi1 = sbias[oc + 1];
#pragma unroll
                for (int p = 0; p < 2; p++) {
                    int blk = blk0 + p * 2;        // 0..15
                    float w0 = fmaxf(alpha * (p ? v2 : v0) + bi0, 0.f);
                    float w1 = fmaxf(alpha * (p ? v3 : v1) + bi1, 0.f);
                    ushort2 stv;
                    stv.x = __half_as_ushort(__float2half(w0));
                    stv.y = __half_as_ushort(__float2half(w1));
                    *(ushort2*)((unsigned short*)g_act3 + (img * 16 + blk) * 256 + oc) = stv;
                }
            }
        }
    }
}

// ========================= fc1 (split-K 8) ==================================
#define F1_SA 0
#define F1_SB 18432
#define F1_SMEM 36880
__global__ __launch_bounds__(256, 2) void k_fc1f() {
    extern __shared__ __align__(128) char smem[];
    uint32_t sbase = smem_u32(smem);
    int tid = threadIdx.x, wid = tid >> 5, lane = tid & 31;
    int m0 = blockIdx.x * 128, o0 = blockIdx.y * 128, k0 = blockIdx.z * 512;

    int row = tid >> 1, half = tid & 1;

    float acc[16][4];
#pragma unroll
    for (int i = 0; i < 16; i++)
#pragma unroll
        for (int j = 0; j < 4; j++) acc[i][j] = 0.f;

    int arow_l = wid * 16 + (lane & 15);
    uint32_t khalf16 = (uint32_t)((lane >> 4) << 4);
    uint32_t aAddr = sbase + F1_SA + (uint32_t)arow_l * 144 + khalf16;
    uint32_t bAddr0 = sbase + F1_SB + (uint32_t)(lane & 15) * 144 + khalf16;

    for (int st = 0; st < 8; st++) {
        int koff = k0 + st * 64;
        __syncthreads();
        {
            const h16* srcA = g_act3 + (m0 + row) * 4096 + koff + half * 32;
            const h16* srcB = g_wf1s + (o0 + row) * 4096 + koff + half * 32;
            char* dA = smem + F1_SA + row * 144 + half * 64;
            char* dB = smem + F1_SB + row * 144 + half * 64;
#pragma unroll
            for (int j = 0; j < 4; j++) {
                *(uint4*)(dA + j * 16) = *(const uint4*)(srcA + j * 8);
                *(uint4*)(dB + j * 16) = *(const uint4*)(srcB + j * 8);
            }
        }
        __syncthreads();
#pragma unroll
        for (int kc = 0; kc < 4; kc++) {
            uint32_t kofs = (uint32_t)(kc * 32);
            uint32_t a0, a1, a2, a3;
            ldsm4(aAddr + kofs, a0, a1, a2, a3);
#pragma unroll
            for (int nt2 = 0; nt2 < 8; nt2++) {
                uint32_t r0, r1, r2, r3;
                ldsm4(bAddr0 + kofs + nt2 * 2304, r0, r1, r2, r3);
                mmaf16(acc[2 * nt2],     a0, a1, a2, a3, r0, r2);
                mmaf16(acc[2 * nt2 + 1], a0, a1, a2, a3, r1, r3);
            }
        }
    }

    float* dst = g_fc1p + (long)blockIdx.z * (NB * 256);
    int g = lane >> 2, t2 = lane & 3;
    int orow = m0 + wid * 16 + g;
#pragma unroll
    for (int nt = 0; nt < 16; nt++) {
        int col = o0 + nt * 8 + t2 * 2;
        float2 p0; p0.x = acc[nt][0]; p0.y = acc[nt][1];
        float2 p1; p1.x = acc[nt][2]; p1.y = acc[nt][3];
        *(float2*)(dst + orow * 256 + col) = p0;
        *(float2*)(dst + (orow + 8) * 256 + col) = p1;
    }
}

// ========================= fc1red + fc2 fused (320 thr = 10 warps) ==========
__global__ void k_fcout(const float* __restrict__ bf1, const float* __restrict__ bf2,
                        float* __restrict__ out) {
    __shared__ float a[256];
    int n = blockIdx.x, tid = threadIdx.x;
    float al3 = g_alpha[3], al4 = g_alpha[4];
    if (tid < 256) {
        float v = 0.f;
#pragma unroll
        for (int s = 0; s < 8; s++) v += g_fc1p[(long)s * NB * 256 + n * 256 + tid];
        a[tid] = fmaxf(al3 * v + bf1[tid], 0.f);
    }
    __syncthreads();
    int w = tid >> 5, l = tid & 31;
    const float* wr = &g_wf2t[w * 256];
    float s = 0.f;
#pragma unroll
    for (int k = 0; k < 8; k++) s += a[l + 32 * k] * wr[l + 32 * k];
#pragma unroll
    for (int off = 16; off; off >>= 1) s += __shfl_xor_sync(0xffffffffu, s, off);
    if (l == 0) out[n * 10 + w] = al4 * s + bf2[w];
}

// ========================= launch ===========================================
extern "C" void kernel_launch(void* const* d_in, const int* in_sizes, int n_in,
                              void* d_out, int out_size) {
    const float* x   = (const float*)d_in[0];
    const float* w1  = (const float*)d_in[1];
    const float* b1  = (const float*)d_in[2];
    const float* w2  = (const float*)d_in[3];
    const float* b2  = (const float*)d_in[4];
    const float* w3  = (const float*)d_in[5];
    const float* b3  = (const float*)d_in[6];
    const float* wf1 = (const float*)d_in[7];
    const float* bf1 = (const float*)d_in[8];
    const float* wf2 = (const float*)d_in[9];
    const float* bf2 = (const float*)d_in[10];
    float* out = (float*)d_out;

    static int configured = 0;
    if (!configured) {
        cudaFuncSetAttribute(k_conv1t, cudaFuncAttributeMaxDynamicSharedMemorySize, C1_SMEM);
        cudaFuncSetAttribute(k_conv2f, cudaFuncAttributeMaxDynamicSharedMemorySize, C2_SMEM);
        cudaFuncSetAttribute(k_conv3f, cudaFuncAttributeMaxDynamicSharedMemorySize, C3_SMEM);
        cudaFuncSetAttribute(k_fc1f,   cudaFuncAttributeMaxDynamicSharedMemorySize, F1_SMEM);
        configured = 1;
    }

    k_tern1<<<dim3(128, 5), 256>>>(w1, w2, w3, wf1, wf2);
    k_tern2<<<dim3(256, 5), 256>>>(w1, w2, w3, wf1, wf2);
    k_conv1t<<<NB * 4, 256, C1_SMEM>>>(x, b1);
    k_conv2f<<<NB * 2, 256, C2_SMEM>>>(b2);
    k_conv3f<<<NB, 256, C3_SMEM>>>(b3);
    k_fc1f<<<dim3(8, 2, 8), 256, F1_SMEM>>>();
    k_fcout<<<NB, 320>>>(bf1, bf2, out);
}

// round 16
// speedup vs baseline: 1.0065x; 1.0065x over previous
#include <cuda_runtime.h>
#include <cuda_fp16.h>
#include <math.h>
#include <stdint.h>

// ---------------------------------------------------------------------------
// TernaryCIFAR10Net forward, B=1024 — fp16 mma.sync; bulk-copy staging;
// 256-thread conv CTAs (2/SM). tern2 uses destination-contiguous 8-wide
// vector stores; fc1 uses split-K 16 to fill the chip.
// ---------------------------------------------------------------------------

#define NB 1024
typedef unsigned long long u64;
typedef __half h16;

__device__ __forceinline__ uint32_t smem_u32(const void* p) {
    uint32_t a;
    asm("{ .reg .u64 t; cvta.to.shared.u64 t, %1; cvt.u32.u64 %0, t; }" : "=r"(a) : "l"(p));
    return a;
}
__device__ __forceinline__ void ldsm4(uint32_t addr, uint32_t& r0, uint32_t& r1,
                                      uint32_t& r2, uint32_t& r3) {
    asm volatile("ldmatrix.sync.aligned.m8n8.x4.shared.b16 {%0,%1,%2,%3}, [%4];"
                 : "=r"(r0), "=r"(r1), "=r"(r2), "=r"(r3) : "r"(addr));
}
__device__ __forceinline__ void mmaf16(float* d, uint32_t a0, uint32_t a1, uint32_t a2,
                                       uint32_t a3, uint32_t b0, uint32_t b1) {
    asm volatile("mma.sync.aligned.m16n8k16.row.col.f32.f16.f16.f32 "
                 "{%0,%1,%2,%3}, {%4,%5,%6,%7}, {%8,%9}, {%0,%1,%2,%3};"
                 : "+f"(d[0]), "+f"(d[1]), "+f"(d[2]), "+f"(d[3])
                 : "r"(a0), "r"(a1), "r"(a2), "r"(a3), "r"(b0), "r"(b1));
}
#define MBAR_INIT(mbar, count) \
    asm volatile("mbarrier.init.shared.b64 [%0], %1;" :: "r"((uint32_t)(mbar)), "r"((uint32_t)(count)) : "memory")
#define MBAR_EXPECT(mbar, bytes) \
    asm volatile("mbarrier.arrive.expect_tx.shared.b64 _, [%0], %1;" \
                 :: "r"((uint32_t)(mbar)), "r"((uint32_t)(bytes)) : "memory")
#define MBAR_WAIT(mbar, parity) do {                                                         \
    uint32_t _m = (uint32_t)(mbar); uint32_t _p = (uint32_t)(parity); uint32_t _done;        \
    asm volatile("{\n\t.reg .pred p;\n\t"                                                    \
        "mbarrier.try_wait.parity.acquire.cta.shared::cta.b64 p, [%1], %2;\n\t"              \
        "selp.b32 %0, 1, 0, p;\n\t}" : "=r"(_done) : "r"(_m), "r"(_p) : "memory");           \
    if (!_done) {                                                                            \
        asm volatile("{\n\t.reg .pred P1;\n\t"                                               \
            "WAIT_LOOP_%=:\n\t"                                                              \
            "mbarrier.try_wait.parity.acquire.cta.shared::cta.b64 P1, [%0], %1, 0x989680;\n\t" \
            "@P1 bra.uni WAIT_DONE_%=;\n\t"                                                  \
            "bra.uni WAIT_LOOP_%=;\n\t"                                                      \
            "WAIT_DONE_%=:\n\t}" :: "r"(_m), "r"(_p) : "memory");                            \
    }                                                                                        \
} while (0)
#define BULK_LD(dst, src, bytes, mbar) \
    asm volatile("{\n\t.reg .u64 g;\n\tcvta.to.global.u64 g, %1;\n\t" \
        "cp.async.bulk.shared::cluster.global.mbarrier::complete_tx::bytes [%0], [g], %2, [%3];\n\t}" \
        :: "r"((uint32_t)(dst)), "l"(src), "r"((uint32_t)(bytes)), "r"((uint32_t)(mbar)) : "memory")

// ========================= device scratch ===================================
#define A1R 23360
#define A2R 13632
__device__ __align__(16) h16 g_a1[NB * A1R];
__device__ __align__(16) h16 g_a2[NB * A2R];
__device__ __align__(16) h16 g_act3[NB * 16 * 256]; // [n][s][c]
__device__ float g_fc1p[16 * NB * 256];

__device__ __align__(16) h16 g_w1s[64 * 72];           // [oc][k pad72]
__device__ __align__(16) h16 g_w2s[9 * 128 * 72];      // [tap][oc][ic pad72]
__device__ __align__(16) h16 g_w3s[9 * 2 * 256 * 72];  // [tap][ichalf][oc][ic64 pad72]
__device__ __align__(16) h16 g_wf1s[256 * 4096];       // [o][k'], k'=s*256+c
__device__ float g_wf2t[10 * 256];

__device__ float g_p1[5][128];
__device__ int   g_c1[5];
__device__ float g_p2s[5][256];
__device__ float g_p2c[5][256];
__device__ int   g_c2[5];
__device__ float g_delta[5];
__device__ float g_alpha[5];

__constant__ int c_n[5] = {64 * 3 * 9, 128 * 64 * 9, 256 * 128 * 9, 256 * 4096, 10 * 256};

__device__ __forceinline__ const float* pick_src(int t, const float* a, const float* b,
                                                 const float* c, const float* d, const float* e) {
    switch (t) { case 0: return a; case 1: return b; case 2: return c; case 3: return d; default: return e; }
}

// ========================= ternarization (2 kernels) ========================
__global__ void k_tern1(const float* __restrict__ a, const float* __restrict__ b,
                        const float* __restrict__ c, const float* __restrict__ d,
                        const float* __restrict__ e) {
    int t = blockIdx.y, tid = threadIdx.x;
    const float* w = pick_src(t, a, b, c, d, e);
    int n = c_n[t];
    float s = 0.f;
    for (int i = blockIdx.x * 256 + tid; i < n; i += 128 * 256) s += fabsf(w[i]);
    __shared__ float sm[256];
    __shared__ int slast;
    sm[tid] = s; __syncthreads();
    for (int st = 128; st > 0; st >>= 1) {
        if (tid < st) sm[tid] += sm[tid + st];
        __syncthreads();
    }
    if (tid == 0) {
        g_p1[t][blockIdx.x] = sm[0];
        __threadfence();
        int old = atomicAdd(&g_c1[t], 1);
        slast = (old == 127) ? 1 : 0;
    }
    __syncthreads();
    if (slast) {
        __shared__ float r[128];
        if (tid < 128) r[tid] = g_p1[t][tid];
        __syncthreads();
        for (int st = 64; st > 0; st >>= 1) {
            if (tid < st) r[tid] += r[tid + st];
            __syncthreads();
        }
        if (tid == 0) { g_delta[t] = 0.7f * r[0] / (float)n; g_c1[t] = 0; }
    }
}

// sign write (vectorized dst-contiguous stores) + masked stats + alpha
__global__ void k_tern2(const float* __restrict__ a, const float* __restrict__ b,
                        const float* __restrict__ c, const float* __restrict__ d,
                        const float* __restrict__ e) {
    int t = blockIdx.y, tid = threadIdx.x;
    int n = c_n[t];
    float dlt = g_delta[t];
    float s = 0.f, cn = 0.f;

    if (t == 0 || t == 4) {
        const float* w = pick_src(t, a, b, c, d, e);
        for (int i = blockIdx.x * 256 + tid; i < n; i += 256 * 256) {
            float v = w[i];
            float av = fabsf(v);
            float sg;
            if (av > dlt) { s += av; cn += 1.f; sg = (v > 0.f ? 1.f : -1.f); } else sg = 0.f;
            if (t == 0) { int oc = i / 27, r = i - oc * 27; g_w1s[oc * 72 + r] = __float2half(sg); }
            else g_wf2t[i] = sg;
        }
    } else {
        int ng = n >> 3;   // groups of 8 along dst-contiguous axis
        for (int g = blockIdx.x * 256 + tid; g < ng; g += 256 * 256) {
            const float* src;
            int stride;
            h16* dst;
            if (t == 1) {
                int u = g >> 3, icc = g & 7;
                int oc = u / 9, k = u - oc * 9;
                src = b + oc * 576 + (icc * 8) * 9 + k; stride = 9;
                dst = g_w2s + (k * 128 + oc) * 72 + icc * 8;
            } else if (t == 2) {
                int u = g >> 3, icc = g & 7;
                int row = u;                         // row = (k*2+ih)*256 + oc
                int oc = row & 255, kh = row >> 8;   // kh = k*2+ih
                int ih = kh & 1, k = kh >> 1;
                src = c + oc * 1152 + (ih * 64 + icc * 8) * 9 + k; stride = 9;
                dst = g_w3s + row * 72 + icc * 8;
            } else {
                int u = g >> 5, chc = g & 31;        // u = o*16+s4
                int s4 = u & 15, o = u >> 4;
                src = d + o * 4096 + (chc * 8) * 16 + s4; stride = 16;
                dst = g_wf1s + o * 4096 + s4 * 256 + chc * 8;
            }
            unsigned short hh[8];
#pragma unroll
            for (int j = 0; j < 8; j++) {
                float v = src[j * stride];
                float av = fabsf(v);
                float sg;
                if (av > dlt) { s += av; cn += 1.f; sg = (v > 0.f ? 1.f : -1.f); } else sg = 0.f;
                hh[j] = __half_as_ushort(__float2half(sg));
            }
            *(uint4*)dst = *(uint4*)hh;
        }
    }

    __shared__ float sm[256], sc[256];
    __shared__ int slast;
    sm[tid] = s; sc[tid] = cn; __syncthreads();
    for (int st = 128; st > 0; st >>= 1) {
        if (tid < st) { sm[tid] += sm[tid + st]; sc[tid] += sc[tid + st]; }
        __syncthreads();
    }
    if (tid == 0) {
        g_p2s[t][blockIdx.x] = sm[0];
        g_p2c[t][blockIdx.x] = sc[0];
        __threadfence();
        int old = atomicAdd(&g_c2[t], 1);
        slast = (old == 255) ? 1 : 0;
    }
    __syncthreads();
    if (slast) {
        sm[tid] = g_p2s[t][tid];
        sc[tid] = g_p2c[t][tid];
        __syncthreads();
        for (int st = 128; st > 0; st >>= 1) {
            if (tid < st) { sm[tid] += sm[tid + st]; sc[tid] += sc[tid + st]; }
            __syncthreads();
        }
        if (tid == 0) { g_alpha[t] = sm[0] / fmaxf(sc[0], 1.f); g_c2[t] = 0; }
    }
}

// ========================= conv1: 3->64 (tensor, im2col) ====================
#define C1_SIN 0
#define C1_A 4096
#define C1_B 40960
#define C1_BIAS 50176
#define C1_SMEM 50448
__global__ __launch_bounds__(256, 2) void k_conv1t(const float* __restrict__ x,
                                                   const float* __restrict__ b1) {
    extern __shared__ __align__(128) char smem[];
    uint32_t sbase = smem_u32(smem);
    int tid = threadIdx.x, wid = tid >> 5, lane = tid & 31;
    int n = blockIdx.x >> 2, q = blockIdx.x & 3;
    float* sinp = (float*)(smem + C1_SIN);
    float* sbias = (float*)(smem + C1_BIAS);
    if (tid < 64) sbias[tid] = b1[tid];

    for (int i = tid; i < 1020; i += 256) {
        int c = i / 340, r = i - c * 340, yy = r / 34, xx = r - yy * 34;
        int gy = q * 8 + yy - 1, gx = xx - 1;
        float v = 0.f;
        if (gy >= 0 && gy < 32 && gx >= 0 && gx < 32)
            v = x[((n * 3 + c) * 32 + gy) * 32 + gx];
        sinp[i] = v;
    }
    for (int i = tid; i < 576; i += 256)
        *(uint4*)(smem + C1_B + i * 16) = ((const uint4*)g_w1s)[i];
    __syncthreads();

    {
        int b = tid >> 2, c = tid & 3;
        int by = b >> 4, bx = b & 15;
        int y0 = by * 2 + (c >> 1), x0 = bx * 2 + (c & 1);
        unsigned short hh[32];
#pragma unroll
        for (int k = 0; k < 27; k++) {
            int ch = k / 9, r = k - ch * 9, ky = r / 3, kx = r - ky * 3;
            hh[k] = __half_as_ushort(__float2half(sinp[(ch * 10 + y0 + ky) * 34 + x0 + kx]));
        }
#pragma unroll
        for (int k = 27; k < 32; k++) hh[k] = 0;
        char* dst = smem + C1_A + tid * 144;
#pragma unroll
        for (int j = 0; j < 4; j++) *(uint4*)(dst + j * 16) = *(uint4*)&hh[j * 8];
    }
    __syncthreads();

    float alpha = g_alpha[0];
    uint32_t khalf16 = (uint32_t)((lane >> 4) << 4);
    uint32_t bRowOff = sbase + C1_B + (uint32_t)(lane & 15) * 144 + khalf16;
    uint32_t bf[2][4][4];
#pragma unroll
    for (int kc = 0; kc < 2; kc++)
#pragma unroll
        for (int nt2 = 0; nt2 < 4; nt2++)
            ldsm4(bRowOff + kc * 32 + nt2 * 2304,
                  bf[kc][nt2][0], bf[kc][nt2][1], bf[kc][nt2][2], bf[kc][nt2][3]);

    int t2 = lane & 3;
    bool wr = (lane & 12) == 0;
#pragma unroll
    for (int h = 0; h < 2; h++) {
        int mt = wid + 8 * h;
        uint32_t aAddr = sbase + C1_A + (uint32_t)(mt * 16 + (lane & 15)) * 144 + khalf16;
        float acc[8][4];
#pragma unroll
        for (int i = 0; i < 8; i++)
#pragma unroll
            for (int j = 0; j < 4; j++) acc[i][j] = 0.f;
#pragma unroll
        for (int kc = 0; kc < 2; kc++) {
            uint32_t a0, a1, a2, a3;
            ldsm4(aAddr + kc * 32, a0, a1, a2, a3);
#pragma unroll
            for (int nt2 = 0; nt2 < 4; nt2++) {
                mmaf16(acc[2 * nt2],     a0, a1, a2, a3, bf[kc][nt2][0], bf[kc][nt2][2]);
                mmaf16(acc[2 * nt2 + 1], a0, a1, a2, a3, bf[kc][nt2][1], bf[kc][nt2][3]);
            }
        }
        int blk0 = mt * 4 + (lane >> 4);
#pragma unroll
        for (int nt = 0; nt < 8; nt++) {
            float v0 = acc[nt][0], v1 = acc[nt][1], v2 = acc[nt][2], v3 = acc[nt][3];
            v0 = fmaxf(v0, __shfl_xor_sync(0xffffffffu, v0, 4));
            v0 = fmaxf(v0, __shfl_xor_sync(0xffffffffu, v0, 8));
            v1 = fmaxf(v1, __shfl_xor_sync(0xffffffffu, v1, 4));
            v1 = fmaxf(v1, __shfl_xor_sync(0xffffffffu, v1, 8));
            v2 = fmaxf(v2, __shfl_xor_sync(0xffffffffu, v2, 4));
            v2 = fmaxf(v2, __shfl_xor_sync(0xffffffffu, v2, 8));
            v3 = fmaxf(v3, __shfl_xor_sync(0xffffffffu, v3, 4));
            v3 = fmaxf(v3, __shfl_xor_sync(0xffffffffu, v3, 8));
            if (wr) {
                int oc = nt * 8 + t2 * 2;
                float bi0 = sbias[oc], bi1 = sbias[oc + 1];
#pragma unroll
                for (int p = 0; p < 2; p++) {
                    int blk = blk0 + p * 2;
                    float w0 = fmaxf(alpha * (p ? v2 : v0) + bi0, 0.f);
                    float w1 = fmaxf(alpha * (p ? v3 : v1) + bi1, 0.f);
                    int py = q * 4 + (blk >> 4), px = blk & 15;
                    int pl = (py + 1) * 18 + (px + 1);
                    ushort2 st;
                    st.x = __half_as_ushort(__float2half(w0));
                    st.y = __half_as_ushort(__float2half(w1));
                    *(ushort2*)((unsigned short*)g_a1 + n * A1R + pl * 72 +
                                (((py + 1) & 1) << 4) + oc) = st;
                }
            }
        }
    }
}

// ========================= conv2: 64->128 (256 thr, half image, 2 CTA/SM) ===
#define C2_HALO 0
#define C2_B0 25984
#define C2_BSZ 18432
#define C2_BIAS (C2_B0 + 4 * C2_BSZ)
#define C2_MBAR (C2_BIAS + 512)
#define C2_SMEM (C2_MBAR + 48)
__global__ __launch_bounds__(256, 2) void k_conv2f(const float* __restrict__ b2) {
    extern __shared__ __align__(128) char smem[];
    uint32_t sb = smem_u32(smem);
    int tid = threadIdx.x, wid = tid >> 5, lane = tid & 31;
    int wm = wid & 3, wn = wid >> 2;
    int n = blockIdx.x >> 1, hf = blockIdx.x & 1;
    float* sbias = (float*)(smem + C2_BIAS);
    if (tid < 128) sbias[tid] = b2[tid];

    if (tid == 0) {
#pragma unroll
        for (int i = 0; i < 5; i++) MBAR_INIT(sb + C2_MBAR + i * 8, 1);
    }
    __syncthreads();
    if (tid == 0) {
        MBAR_EXPECT(sb + C2_MBAR + 32, 25952);
        BULK_LD(sb + C2_HALO, (const char*)g_a1 + (size_t)n * 46720 + hf * 20736,
                25952, sb + C2_MBAR + 32);
        MBAR_EXPECT(sb + C2_MBAR + 0, C2_BSZ);
        BULK_LD(sb + C2_B0, (const char*)g_w2s, C2_BSZ, sb + C2_MBAR + 0);
        MBAR_EXPECT(sb + C2_MBAR + 8, C2_BSZ);
        BULK_LD(sb + C2_B0 + C2_BSZ, (const char*)g_w2s + C2_BSZ, C2_BSZ, sb + C2_MBAR + 8);
    }

    int y_m[2], x_m[2];
#pragma unroll
    for (int h = 0; h < 2; h++) {
        int m = (wm + 4 * h) * 16 + (lane & 15);
        int b = m >> 2, c = m & 3;
        y_m[h] = ((b >> 3) << 1) + (c >> 1);
        x_m[h] = ((b & 7) << 1) + (c & 1);
    }
    uint32_t khalf16 = (uint32_t)((lane >> 4) << 4);
    uint32_t bRowOff = (uint32_t)(wn * 64 + (lane & 15)) * 144 + khalf16;

    float acc[2][8][4];
#pragma unroll
    for (int h = 0; h < 2; h++)
#pragma unroll
        for (int i = 0; i < 8; i++)
#pragma unroll
            for (int j = 0; j < 4; j++) acc[h][i][j] = 0.f;

    MBAR_WAIT(sb + C2_MBAR + 32, 0);

    for (int tap = 0; tap < 9; tap++) {
        if (tid == 0 && tap + 2 < 9) {
            int nx = tap + 2;
            MBAR_EXPECT(sb + C2_MBAR + (nx & 3) * 8, C2_BSZ);
            BULK_LD(sb + C2_B0 + (nx & 3) * C2_BSZ, (const char*)g_w2s + nx * C2_BSZ,
                    C2_BSZ, sb + C2_MBAR + (nx & 3) * 8);
        }
        MBAR_WAIT(sb + C2_MBAR + (tap & 3) * 8, (tap >> 2) & 1);

        int ky = tap / 3, kx = tap - ky * 3;
        uint32_t aA[2];
#pragma unroll
        for (int h = 0; h < 2; h++) {
            int hy = y_m[h] + ky;
            aA[h] = sb + C2_HALO + (uint32_t)(hy * 18 + x_m[h] + kx) * 144 +
                    (uint32_t)((hy & 1) << 5) + khalf16;
        }
        uint32_t bBuf = sb + C2_B0 + (uint32_t)((tap & 3) * C2_BSZ);
#pragma unroll
        for (int kc = 0; kc < 4; kc++) {
            uint32_t a00, a01, a02, a03, a10, a11, a12, a13;
            ldsm4(aA[0] + kc * 32, a00, a01, a02, a03);
            ldsm4(aA[1] + kc * 32, a10, a11, a12, a13);
#pragma unroll
            for (int nt2 = 0; nt2 < 4; nt2++) {
                uint32_t r0, r1, r2, r3;
                ldsm4(bBuf + bRowOff + nt2 * 2304 + kc * 32, r0, r1, r2, r3);
                mmaf16(acc[0][2 * nt2],     a00, a01, a02, a03, r0, r2);
                mmaf16(acc[0][2 * nt2 + 1], a00, a01, a02, a03, r1, r3);
                mmaf16(acc[1][2 * nt2],     a10, a11, a12, a13, r0, r2);
                mmaf16(acc[1][2 * nt2 + 1], a10, a11, a12, a13, r1, r3);
            }
        }
        __syncthreads();
    }

    float alpha = g_alpha[1];
    int t2 = lane & 3;
    bool wr = (lane & 12) == 0;
#pragma unroll
    for (int h = 0; h < 2; h++) {
        int mt = hf * 8 + wm + 4 * h;
        int blk0 = mt * 4 + (lane >> 4);
#pragma unroll
        for (int nt = 0; nt < 8; nt++) {
            float v0 = acc[h][nt][0], v1 = acc[h][nt][1], v2 = acc[h][nt][2], v3 = acc[h][nt][3];
            v0 = fmaxf(v0, __shfl_xor_sync(0xffffffffu, v0, 4));
            v0 = fmaxf(v0, __shfl_xor_sync(0xffffffffu, v0, 8));
            v1 = fmaxf(v1, __shfl_xor_sync(0xffffffffu, v1, 4));
            v1 = fmaxf(v1, __shfl_xor_sync(0xffffffffu, v1, 8));
            v2 = fmaxf(v2, __shfl_xor_sync(0xffffffffu, v2, 4));
            v2 = fmaxf(v2, __shfl_xor_sync(0xffffffffu, v2, 8));
            v3 = fmaxf(v3, __shfl_xor_sync(0xffffffffu, v3, 4));
            v3 = fmaxf(v3, __shfl_xor_sync(0xffffffffu, v3, 8));
            if (wr) {
                int oc = wn * 64 + nt * 8 + t2 * 2;
                float bi0 = sbias[oc], bi1 = sbias[oc + 1];
#pragma unroll
                for (int p = 0; p < 2; p++) {
                    int blk = blk0 + p * 2;
                    float w0 = fmaxf(alpha * (p ? v2 : v0) + bi0, 0.f);
                    float w1 = fmaxf(alpha * (p ? v3 : v1) + bi1, 0.f);
                    int py = blk >> 3, px = blk & 7;
                    int pl = (py + 1) * 10 + (px + 1);
                    ushort2 st;
                    st.x = __half_as_ushort(__float2half(w0));
                    st.y = __half_as_ushort(__float2half(w1));
                    *(ushort2*)((unsigned short*)g_a2 + n * A2R + pl * 136 +
                                (((py + 1) & 1) << 4) + oc) = st;
                }
            }
        }
    }
}

// ========================= conv3: 2 images x 128 oc per CTA ================
#define C3_HALO 0
#define C3_B0 54528
#define C3_BSZ 18432
#define C3_BIAS (C3_B0 + 2 * C3_BSZ)
#define C3_MBAR (C3_BIAS + 1024)
#define C3_SMEM (C3_MBAR + 32)
__global__ __launch_bounds__(256, 2) void k_conv3f(const float* __restrict__ b3) {
    extern __shared__ __align__(128) char smem[];
    uint32_t sb = smem_u32(smem);
    int tid = threadIdx.x, wid = tid >> 5, lane = tid & 31;
    int wm = wid & 3, wn = wid >> 2;
    int pr = blockIdx.x >> 1, oh = blockIdx.x & 1;
    int n0 = pr * 2;
    float* sbias = (float*)(smem + C3_BIAS);
    sbias[tid] = b3[tid];

    if (tid == 0) {
#pragma unroll
        for (int i = 0; i < 3; i++) MBAR_INIT(sb + C3_MBAR + i * 8, 1);
    }
    __syncthreads();
    if (tid == 0) {
        MBAR_EXPECT(sb + C3_MBAR + 16, 2 * 27264);
        BULK_LD(sb + C3_HALO,         (const char*)g_a2 + (size_t)n0 * 27264,       27264, sb + C3_MBAR + 16);
        BULK_LD(sb + C3_HALO + 27264, (const char*)g_a2 + (size_t)(n0 + 1) * 27264, 27264, sb + C3_MBAR + 16);
        MBAR_EXPECT(sb + C3_MBAR + 0, C3_BSZ);
        BULK_LD(sb + C3_B0, (const char*)g_w3s + (size_t)(oh * 128) * 144, C3_BSZ, sb + C3_MBAR + 0);
    }

    int y_m[2], x_m[2], img_m[2];
#pragma unroll
    for (int h = 0; h < 2; h++) {
        int m = (wm + 4 * h) * 16 + (lane & 15);
        img_m[h] = m >> 6;
        int r = m & 63;
        int bl = r >> 2, c = r & 3;
        y_m[h] = ((bl >> 2) << 1) + (c >> 1);
        x_m[h] = ((bl & 3) << 1) + (c & 1);
    }
    uint32_t khalf16 = (uint32_t)((lane >> 4) << 4);
    uint32_t bRowOff = (uint32_t)(wn * 64 + (lane & 15)) * 144 + khalf16;

    float acc[2][8][4];
#pragma unroll
    for (int h = 0; h < 2; h++)
#pragma unroll
        for (int i = 0; i < 8; i++)
#pragma unroll
            for (int j = 0; j < 4; j++) acc[h][i][j] = 0.f;

    MBAR_WAIT(sb + C3_MBAR + 16, 0);

    for (int st = 0; st < 18; st++) {
        if (tid == 0 && st + 1 < 18) {
            int nx = st + 1;
            MBAR_EXPECT(sb + C3_MBAR + (nx & 1) * 8, C3_BSZ);
            BULK_LD(sb + C3_B0 + (nx & 1) * C3_BSZ,
                    (const char*)g_w3s + (size_t)(nx * 256 + oh * 128) * 144,
                    C3_BSZ, sb + C3_MBAR + (nx & 1) * 8);
        }
        MBAR_WAIT(sb + C3_MBAR + (st & 1) * 8, (st >> 1) & 1);

        int tap = st >> 1, chalf = (st & 1) * 128;
        int ky = tap / 3, kx = tap - ky * 3;
        uint32_t aA[2];
#pragma unroll
        for (int h = 0; h < 2; h++) {
            int hy = y_m[h] + ky;
            aA[h] = sb + C3_HALO + (uint32_t)(img_m[h] * 27264) +
                    (uint32_t)(hy * 10 + x_m[h] + kx) * 272 +
                    (uint32_t)((hy & 1) << 5) + (uint32_t)chalf + khalf16;
        }
        uint32_t bBuf = sb + C3_B0 + (uint32_t)((st & 1) * C3_BSZ);
#pragma unroll
        for (int kc = 0; kc < 4; kc++) {
            uint32_t a00, a01, a02, a03, a10, a11, a12, a13;
            ldsm4(aA[0] + kc * 32, a00, a01, a02, a03);
            ldsm4(aA[1] + kc * 32, a10, a11, a12, a13);
#pragma unroll
            for (int nt2 = 0; nt2 < 4; nt2++) {
                uint32_t r0, r1, r2, r3;
                ldsm4(bBuf + bRowOff + nt2 * 2304 + kc * 32, r0, r1, r2, r3);
                mmaf16(acc[0][2 * nt2],     a00, a01, a02, a03, r0, r2);
                mmaf16(acc[0][2 * nt2 + 1], a00, a01, a02, a03, r1, r3);
                mmaf16(acc[1][2 * nt2],     a10, a11, a12, a13, r0, r2);
                mmaf16(acc[1][2 * nt2 + 1], a10, a11, a12, a13, r1, r3);
            }
        }
        __syncthreads();
    }

    float alpha = g_alpha[2];
    int t2 = lane & 3;
    bool wr = (lane & 12) == 0;
#pragma unroll
    for (int h = 0; h < 2; h++) {
        int mt = wm + 4 * h;
        int img = n0 + (mt >> 2);
        int blk0 = (mt & 3) * 4 + (lane >> 4);
#pragma unroll
        for (int nt = 0; nt < 8; nt++) {
            float v0 = acc[h][nt][0], v1 = acc[h][nt][1], v2 = acc[h][nt][2], v3 = acc[h][nt][3];
            v0 = fmaxf(v0, __shfl_xor_sync(0xffffffffu, v0, 4));
            v0 = fmaxf(v0, __shfl_xor_sync(0xffffffffu, v0, 8));
            v1 = fmaxf(v1, __shfl_xor_sync(0xffffffffu, v1, 4));
            v1 = fmaxf(v1, __shfl_xor_sync(0xffffffffu, v1, 8));
            v2 = fmaxf(v2, __shfl_xor_sync(0xffffffffu, v2, 4));
            v2 = fmaxf(v2, __shfl_xor_sync(0xffffffffu, v2, 8));
            v3 = fmaxf(v3, __shfl_xor_sync(0xffffffffu, v3, 4));
            v3 = fmaxf(v3, __shfl_xor_sync(0xffffffffu, v3, 8));
            if (wr) {
                int oc = oh * 128 + wn * 64 + nt * 8 + t2 * 2;
                float bi0 = sbias[oc], bi1 = sbias[oc + 1];
#pragma unroll
                for (int p = 0; p < 2; p++) {
                    int blk = blk0 + p * 2;
                    float w0 = fmaxf(alpha * (p ? v2 : v0) + bi0, 0.f);
                    float w1 = fmaxf(alpha * (p ? v3 : v1) + bi1, 0.f);
                    ushort2 stv;
                    stv.x = __half_as_ushort(__float2half(w0));
                    stv.y = __half_as_ushort(__float2half(w1));
                    *(ushort2*)((unsigned short*)g_act3 + (img * 16 + blk) * 256 + oc) = stv;
                }
            }
        }
    }
}

// ========================= fc1 (split-K 16) =================================
#define F1_SA 0
#define F1_SB 18432
#define F1_SMEM 36880
__global__ __launch_bounds__(256, 2) void k_fc1f() {
    extern __shared__ __align__(128) char smem[];
    uint32_t sbase = smem_u32(smem);
    int tid = threadIdx.x, wid = tid >> 5, lane = tid & 31;
    int m0 = blockIdx.x * 128, o0 = blockIdx.y * 128, k0 = blockIdx.z * 256;

    int row = tid >> 1, half = tid & 1;

    float acc[16][4];
#pragma unroll
    for (int i = 0; i < 16; i++)
#pragma unroll
        for (int j = 0; j < 4; j++) acc[i][j] = 0.f;

    int arow_l = wid * 16 + (lane & 15);
    uint32_t khalf16 = (uint32_t)((lane >> 4) << 4);
    uint32_t aAddr = sbase + F1_SA + (uint32_t)arow_l * 144 + khalf16;
    uint32_t bAddr0 = sbase + F1_SB + (uint32_t)(lane & 15) * 144 + khalf16;

    for (int st = 0; st < 4; st++) {
        int koff = k0 + st * 64;
        __syncthreads();
        {
            const h16* srcA = g_act3 + (m0 + row) * 4096 + koff + half * 32;
            const h16* srcB = g_wf1s + (o0 + row) * 4096 + koff + half * 32;
            char* dA = smem + F1_SA + row * 144 + half * 64;
            char* dB = smem + F1_SB + row * 144 + half * 64;
#pragma unroll
            for (int j = 0; j < 4; j++) {
                *(uint4*)(dA + j * 16) = *(const uint4*)(srcA + j * 8);
                *(uint4*)(dB + j * 16) = *(const uint4*)(srcB + j * 8);
            }
        }
        __syncthreads();
#pragma unroll
        for (int kc = 0; kc < 4; kc++) {
            uint32_t kofs = (uint32_t)(kc * 32);
            uint32_t a0, a1, a2, a3;
            ldsm4(aAddr + kofs, a0, a1, a2, a3);
#pragma unroll
            for (int nt2 = 0; nt2 < 8; nt2++) {
                uint32_t r0, r1, r2, r3;
                ldsm4(bAddr0 + kofs + nt2 * 2304, r0, r1, r2, r3);
                mmaf16(acc[2 * nt2],     a0, a1, a2, a3, r0, r2);
                mmaf16(acc[2 * nt2 + 1], a0, a1, a2, a3, r1, r3);
            }
        }
    }

    float* dst = g_fc1p + (long)blockIdx.z * (NB * 256);
    int g = lane >> 2, t2 = lane & 3;
    int orow = m0 + wid * 16 + g;
#pragma unroll
    for (int nt = 0; nt < 16; nt++) {
        int col = o0 + nt * 8 + t2 * 2;
        float2 p0; p0.x = acc[nt][0]; p0.y = acc[nt][1];
        float2 p1; p1.x = acc[nt][2]; p1.y = acc[nt][3];
        *(float2*)(dst + orow * 256 + col) = p0;
        *(float2*)(dst + (orow + 8) * 256 + col) = p1;
    }
}

// ========================= fc1red + fc2 fused (320 thr = 10 warps) ==========
__global__ void k_fcout(const float* __restrict__ bf1, const float* __restrict__ bf2,
                        float* __restrict__ out) {
    __shared__ float a[256];
    int n = blockIdx.x, tid = threadIdx.x;
    float al3 = g_alpha[3], al4 = g_alpha[4];
    if (tid < 256) {
        float v = 0.f;
#pragma unroll
        for (int s = 0; s < 16; s++) v += g_fc1p[(long)s * NB * 256 + n * 256 + tid];
        a[tid] = fmaxf(al3 * v + bf1[tid], 0.f);
    }
    __syncthreads();
    int w = tid >> 5, l = tid & 31;
    const float* wr = &g_wf2t[w * 256];
    float s = 0.f;
#pragma unroll
    for (int k = 0; k < 8; k++) s += a[l + 32 * k] * wr[l + 32 * k];
#pragma unroll
    for (int off = 16; off; off >>= 1) s += __shfl_xor_sync(0xffffffffu, s, off);
    if (l == 0) out[n * 10 + w] = al4 * s + bf2[w];
}

// ========================= launch ===========================================
extern "C" void kernel_launch(void* const* d_in, const int* in_sizes, int n_in,
                              void* d_out, int out_size) {
    const float* x   = (const float*)d_in[0];
    const float* w1  = (const float*)d_in[1];
    const float* b1  = (const float*)d_in[2];
    const float* w2  = (const float*)d_in[3];
    const float* b2  = (const float*)d_in[4];
    const float* w3  = (const float*)d_in[5];
    const float* b3  = (const float*)d_in[6];
    const float* wf1 = (const float*)d_in[7];
    const float* bf1 = (const float*)d_in[8];
    const float* wf2 = (const float*)d_in[9];
    const float* bf2 = (const float*)d_in[10];
    float* out = (float*)d_out;

    static int configured = 0;
    if (!configured) {
        cudaFuncSetAttribute(k_conv1t, cudaFuncAttributeMaxDynamicSharedMemorySize, C1_SMEM);
        cudaFuncSetAttribute(k_conv2f, cudaFuncAttributeMaxDynamicSharedMemorySize, C2_SMEM);
        cudaFuncSetAttribute(k_conv3f, cudaFuncAttributeMaxDynamicSharedMemorySize, C3_SMEM);
        cudaFuncSetAttribute(k_fc1f,   cudaFuncAttributeMaxDynamicSharedMemorySize, F1_SMEM);
        configured = 1;
    }

    k_tern1<<<dim3(128, 5), 256>>>(w1, w2, w3, wf1, wf2);
    k_tern2<<<dim3(256, 5), 256>>>(w1, w2, w3, wf1, wf2);
    k_conv1t<<<NB * 4, 256, C1_SMEM>>>(x, b1);
    k_conv2f<<<NB * 2, 256, C2_SMEM>>>(b2);
    k_conv3f<<<NB, 256, C3_SMEM>>>(b3);
    k_fc1f<<<dim3(8, 2, 16), 256, F1_SMEM>>>();
    k_fcout<<<NB, 320>>>(bf1, bf2, out);
}

// round 17
// speedup vs baseline: 1.0361x; 1.0294x over previous
#include <cuda_runtime.h>
#include <cuda_fp16.h>
#include <math.h>
#include <stdint.h>

// ---------------------------------------------------------------------------
// TernaryCIFAR10Net forward, B=1024 — fp16 mma.sync; bulk-copy staging;
// 256-thread conv CTAs (2/SM); half2 pooling epilogues; conv2 syncs every
// 2 taps (safe with 4-deep ring + 2-tap lookahead).
// ---------------------------------------------------------------------------

#define NB 1024
typedef unsigned long long u64;
typedef __half h16;

__device__ __forceinline__ uint32_t smem_u32(const void* p) {
    uint32_t a;
    asm("{ .reg .u64 t; cvta.to.shared.u64 t, %1; cvt.u32.u64 %0, t; }" : "=r"(a) : "l"(p));
    return a;
}
__device__ __forceinline__ void ldsm4(uint32_t addr, uint32_t& r0, uint32_t& r1,
                                      uint32_t& r2, uint32_t& r3) {
    asm volatile("ldmatrix.sync.aligned.m8n8.x4.shared.b16 {%0,%1,%2,%3}, [%4];"
                 : "=r"(r0), "=r"(r1), "=r"(r2), "=r"(r3) : "r"(addr));
}
__device__ __forceinline__ void mmaf16(float* d, uint32_t a0, uint32_t a1, uint32_t a2,
                                       uint32_t a3, uint32_t b0, uint32_t b1) {
    asm volatile("mma.sync.aligned.m16n8k16.row.col.f32.f16.f16.f32 "
                 "{%0,%1,%2,%3}, {%4,%5,%6,%7}, {%8,%9}, {%0,%1,%2,%3};"
                 : "+f"(d[0]), "+f"(d[1]), "+f"(d[2]), "+f"(d[3])
                 : "r"(a0), "r"(a1), "r"(a2), "r"(a3), "r"(b0), "r"(b1));
}
// pooled half2: shuffle-max over lanes ^4 and ^8
__device__ __forceinline__ __half2 poolmax2(__half2 v) {
    uint32_t u = *(uint32_t*)&v;
    uint32_t w = __shfl_xor_sync(0xffffffffu, u, 4);
    v = __hmax2(v, *(__half2*)&w);
    u = *(uint32_t*)&v;
    w = __shfl_xor_sync(0xffffffffu, u, 8);
    return __hmax2(v, *(__half2*)&w);
}
#define MBAR_INIT(mbar, count) \
    asm volatile("mbarrier.init.shared.b64 [%0], %1;" :: "r"((uint32_t)(mbar)), "r"((uint32_t)(count)) : "memory")
#define MBAR_EXPECT(mbar, bytes) \
    asm volatile("mbarrier.arrive.expect_tx.shared.b64 _, [%0], %1;" \
                 :: "r"((uint32_t)(mbar)), "r"((uint32_t)(bytes)) : "memory")
#define MBAR_WAIT(mbar, parity) do {                                                         \
    uint32_t _m = (uint32_t)(mbar); uint32_t _p = (uint32_t)(parity); uint32_t _done;        \
    asm volatile("{\n\t.reg .pred p;\n\t"                                                    \
        "mbarrier.try_wait.parity.acquire.cta.shared::cta.b64 p, [%1], %2;\n\t"              \
        "selp.b32 %0, 1, 0, p;\n\t}" : "=r"(_done) : "r"(_m), "r"(_p) : "memory");           \
    if (!_done) {                                                                            \
        asm volatile("{\n\t.reg .pred P1;\n\t"                                               \
            "WAIT_LOOP_%=:\n\t"                                                              \
            "mbarrier.try_wait.parity.acquire.cta.shared::cta.b64 P1, [%0], %1, 0x989680;\n\t" \
            "@P1 bra.uni WAIT_DONE_%=;\n\t"                                                  \
            "bra.uni WAIT_LOOP_%=;\n\t"                                                      \
            "WAIT_DONE_%=:\n\t}" :: "r"(_m), "r"(_p) : "memory");                            \
    }                                                                                        \
} while (0)
#define BULK_LD(dst, src, bytes, mbar) \
    asm volatile("{\n\t.reg .u64 g;\n\tcvta.to.global.u64 g, %1;\n\t" \
        "cp.async.bulk.shared::cluster.global.mbarrier::complete_tx::bytes [%0], [g], %2, [%3];\n\t}" \
        :: "r"((uint32_t)(dst)), "l"(src), "r"((uint32_t)(bytes)), "r"((uint32_t)(mbar)) : "memory")

// ========================= device scratch ===================================
#define A1R 23360
#define A2R 13632
__device__ __align__(16) h16 g_a1[NB * A1R];
__device__ __align__(16) h16 g_a2[NB * A2R];
__device__ __align__(16) h16 g_act3[NB * 16 * 256]; // [n][s][c]
__device__ float g_fc1p[16 * NB * 256];

__device__ __align__(16) h16 g_w1s[64 * 72];           // [oc][k pad72]
__device__ __align__(16) h16 g_w2s[9 * 128 * 72];      // [tap][oc][ic pad72]
__device__ __align__(16) h16 g_w3s[9 * 2 * 256 * 72];  // [tap][ichalf][oc][ic64 pad72]
__device__ __align__(16) h16 g_wf1s[256 * 4096];       // [o][k'], k'=s*256+c
__device__ float g_wf2t[10 * 256];

__device__ float g_p1[5][128];
__device__ int   g_c1[5];
__device__ float g_p2s[5][256];
__device__ float g_p2c[5][256];
__device__ int   g_c2[5];
__device__ float g_delta[5];
__device__ float g_alpha[5];

__constant__ int c_n[5] = {64 * 3 * 9, 128 * 64 * 9, 256 * 128 * 9, 256 * 4096, 10 * 256};

__device__ __forceinline__ const float* pick_src(int t, const float* a, const float* b,
                                                 const float* c, const float* d, const float* e) {
    switch (t) { case 0: return a; case 1: return b; case 2: return c; case 3: return d; default: return e; }
}

// ========================= ternarization (2 kernels) ========================
__global__ void k_tern1(const float* __restrict__ a, const float* __restrict__ b,
                        const float* __restrict__ c, const float* __restrict__ d,
                        const float* __restrict__ e) {
    int t = blockIdx.y, tid = threadIdx.x;
    const float* w = pick_src(t, a, b, c, d, e);
    int n = c_n[t];
    float s = 0.f;
    for (int i = blockIdx.x * 256 + tid; i < n; i += 128 * 256) s += fabsf(w[i]);
    __shared__ float sm[256];
    __shared__ int slast;
    sm[tid] = s; __syncthreads();
    for (int st = 128; st > 0; st >>= 1) {
        if (tid < st) sm[tid] += sm[tid + st];
        __syncthreads();
    }
    if (tid == 0) {
        g_p1[t][blockIdx.x] = sm[0];
        __threadfence();
        int old = atomicAdd(&g_c1[t], 1);
        slast = (old == 127) ? 1 : 0;
    }
    __syncthreads();
    if (slast) {
        __shared__ float r[128];
        if (tid < 128) r[tid] = g_p1[t][tid];
        __syncthreads();
        for (int st = 64; st > 0; st >>= 1) {
            if (tid < st) r[tid] += r[tid + st];
            __syncthreads();
        }
        if (tid == 0) { g_delta[t] = 0.7f * r[0] / (float)n; g_c1[t] = 0; }
    }
}

__global__ void k_tern2(const float* __restrict__ a, const float* __restrict__ b,
                        const float* __restrict__ c, const float* __restrict__ d,
                        const float* __restrict__ e) {
    int t = blockIdx.y, tid = threadIdx.x;
    int n = c_n[t];
    float dlt = g_delta[t];
    float s = 0.f, cn = 0.f;

    if (t == 0 || t == 4) {
        const float* w = pick_src(t, a, b, c, d, e);
        for (int i = blockIdx.x * 256 + tid; i < n; i += 256 * 256) {
            float v = w[i];
            float av = fabsf(v);
            float sg;
            if (av > dlt) { s += av; cn += 1.f; sg = (v > 0.f ? 1.f : -1.f); } else sg = 0.f;
            if (t == 0) { int oc = i / 27, r = i - oc * 27; g_w1s[oc * 72 + r] = __float2half(sg); }
            else g_wf2t[i] = sg;
        }
    } else {
        int ng = n >> 3;
        for (int g = blockIdx.x * 256 + tid; g < ng; g += 256 * 256) {
            const float* src;
            int stride;
            h16* dst;
            if (t == 1) {
                int u = g >> 3, icc = g & 7;
                int oc = u / 9, k = u - oc * 9;
                src = b + oc * 576 + (icc * 8) * 9 + k; stride = 9;
                dst = g_w2s + (k * 128 + oc) * 72 + icc * 8;
            } else if (t == 2) {
                int u = g >> 3, icc = g & 7;
                int row = u;
                int oc = row & 255, kh = row >> 8;
                int ih = kh & 1, k = kh >> 1;
                src = c + oc * 1152 + (ih * 64 + icc * 8) * 9 + k; stride = 9;
                dst = g_w3s + row * 72 + icc * 8;
            } else {
                int u = g >> 5, chc = g & 31;
                int s4 = u & 15, o = u >> 4;
                src = d + o * 4096 + (chc * 8) * 16 + s4; stride = 16;
                dst = g_wf1s + o * 4096 + s4 * 256 + chc * 8;
            }
            unsigned short hh[8];
#pragma unroll
            for (int j = 0; j < 8; j++) {
                float v = src[j * stride];
                float av = fabsf(v);
                float sg;
                if (av > dlt) { s += av; cn += 1.f; sg = (v > 0.f ? 1.f : -1.f); } else sg = 0.f;
                hh[j] = __half_as_ushort(__float2half(sg));
            }
            *(uint4*)dst = *(uint4*)hh;
        }
    }

    __shared__ float sm[256], sc[256];
    __shared__ int slast;
    sm[tid] = s; sc[tid] = cn; __syncthreads();
    for (int st = 128; st > 0; st >>= 1) {
        if (tid < st) { sm[tid] += sm[tid + st]; sc[tid] += sc[tid + st]; }
        __syncthreads();
    }
    if (tid == 0) {
        g_p2s[t][blockIdx.x] = sm[0];
        g_p2c[t][blockIdx.x] = sc[0];
        __threadfence();
        int old = atomicAdd(&g_c2[t], 1);
        slast = (old == 255) ? 1 : 0;
    }
    __syncthreads();
    if (slast) {
        sm[tid] = g_p2s[t][tid];
        sc[tid] = g_p2c[t][tid];
        __syncthreads();
        for (int st = 128; st > 0; st >>= 1) {
            if (tid < st) { sm[tid] += sm[tid + st]; sc[tid] += sc[tid + st]; }
            __syncthreads();
        }
        if (tid == 0) { g_alpha[t] = sm[0] / fmaxf(sc[0], 1.f); g_c2[t] = 0; }
    }
}

// ========================= conv1: 3->64 (tensor, im2col) ====================
#define C1_SIN 0
#define C1_A 4096
#define C1_B 40960
#define C1_BIAS 50176
#define C1_SMEM 50448
__global__ __launch_bounds__(256, 2) void k_conv1t(const float* __restrict__ x,
                                                   const float* __restrict__ b1) {
    extern __shared__ __align__(128) char smem[];
    uint32_t sbase = smem_u32(smem);
    int tid = threadIdx.x, wid = tid >> 5, lane = tid & 31;
    int n = blockIdx.x >> 2, q = blockIdx.x & 3;
    float* sinp = (float*)(smem + C1_SIN);
    __half2* sbias2 = (__half2*)(smem + C1_BIAS);
    if (tid < 32) sbias2[tid] = __floats2half2_rn(b1[2 * tid], b1[2 * tid + 1]);

    for (int i = tid; i < 1020; i += 256) {
        int c = i / 340, r = i - c * 340, yy = r / 34, xx = r - yy * 34;
        int gy = q * 8 + yy - 1, gx = xx - 1;
        float v = 0.f;
        if (gy >= 0 && gy < 32 && gx >= 0 && gx < 32)
            v = x[((n * 3 + c) * 32 + gy) * 32 + gx];
        sinp[i] = v;
    }
    for (int i = tid; i < 576; i += 256)
        *(uint4*)(smem + C1_B + i * 16) = ((const uint4*)g_w1s)[i];
    __syncthreads();

    {
        int b = tid >> 2, c = tid & 3;
        int by = b >> 4, bx = b & 15;
        int y0 = by * 2 + (c >> 1), x0 = bx * 2 + (c & 1);
        unsigned short hh[32];
#pragma unroll
        for (int k = 0; k < 27; k++) {
            int ch = k / 9, r = k - ch * 9, ky = r / 3, kx = r - ky * 3;
            hh[k] = __half_as_ushort(__float2half(sinp[(ch * 10 + y0 + ky) * 34 + x0 + kx]));
        }
#pragma unroll
        for (int k = 27; k < 32; k++) hh[k] = 0;
        char* dst = smem + C1_A + tid * 144;
#pragma unroll
        for (int j = 0; j < 4; j++) *(uint4*)(dst + j * 16) = *(uint4*)&hh[j * 8];
    }
    __syncthreads();

    float alpha = g_alpha[0];
    __half2 z2 = __floats2half2_rn(0.f, 0.f);
    uint32_t khalf16 = (uint32_t)((lane >> 4) << 4);
    uint32_t bRowOff = sbase + C1_B + (uint32_t)(lane & 15) * 144 + khalf16;
    uint32_t bf[2][4][4];
#pragma unroll
    for (int kc = 0; kc < 2; kc++)
#pragma unroll
        for (int nt2 = 0; nt2 < 4; nt2++)
            ldsm4(bRowOff + kc * 32 + nt2 * 2304,
                  bf[kc][nt2][0], bf[kc][nt2][1], bf[kc][nt2][2], bf[kc][nt2][3]);

    int t2 = lane & 3;
    bool wr = (lane & 12) == 0;
#pragma unroll
    for (int h = 0; h < 2; h++) {
        int mt = wid + 8 * h;
        uint32_t aAddr = sbase + C1_A + (uint32_t)(mt * 16 + (lane & 15)) * 144 + khalf16;
        float acc[8][4];
#pragma unroll
        for (int i = 0; i < 8; i++)
#pragma unroll
            for (int j = 0; j < 4; j++) acc[i][j] = 0.f;
#pragma unroll
        for (int kc = 0; kc < 2; kc++) {
            uint32_t a0, a1, a2, a3;
            ldsm4(aAddr + kc * 32, a0, a1, a2, a3);
#pragma unroll
            for (int nt2 = 0; nt2 < 4; nt2++) {
                mmaf16(acc[2 * nt2],     a0, a1, a2, a3, bf[kc][nt2][0], bf[kc][nt2][2]);
                mmaf16(acc[2 * nt2 + 1], a0, a1, a2, a3, bf[kc][nt2][1], bf[kc][nt2][3]);
            }
        }
        int blk0 = mt * 4 + (lane >> 4);
#pragma unroll
        for (int nt = 0; nt < 8; nt++) {
            __half2 p01 = __floats2half2_rn(alpha * acc[nt][0], alpha * acc[nt][1]);
            __half2 p23 = __floats2half2_rn(alpha * acc[nt][2], alpha * acc[nt][3]);
            p01 = poolmax2(p01);
            p23 = poolmax2(p23);
            if (wr) {
                int oc = nt * 8 + t2 * 2;
                __half2 bi = sbias2[oc >> 1];
                p01 = __hmax2(__hadd2(p01, bi), z2);
                p23 = __hmax2(__hadd2(p23, bi), z2);
#pragma unroll
                for (int p = 0; p < 2; p++) {
                    int blk = blk0 + p * 2;
                    int py = q * 4 + (blk >> 4), px = blk & 15;
                    int pl = (py + 1) * 18 + (px + 1);
                    *(__half2*)((unsigned short*)g_a1 + n * A1R + pl * 72 +
                                (((py + 1) & 1) << 4) + oc) = p ? p23 : p01;
                }
            }
        }
    }
}

// ========================= conv2: 64->128 (256 thr, half image, 2 CTA/SM) ===
#define C2_HALO 0
#define C2_B0 25984
#define C2_BSZ 18432
#define C2_BIAS (C2_B0 + 4 * C2_BSZ)
#define C2_MBAR (C2_BIAS + 512)
#define C2_SMEM (C2_MBAR + 48)
__global__ __launch_bounds__(256, 2) void k_conv2f(const float* __restrict__ b2) {
    extern __shared__ __align__(128) char smem[];
    uint32_t sb = smem_u32(smem);
    int tid = threadIdx.x, wid = tid >> 5, lane = tid & 31;
    int wm = wid & 3, wn = wid >> 2;
    int n = blockIdx.x >> 1, hf = blockIdx.x & 1;
    __half2* sbias2 = (__half2*)(smem + C2_BIAS);
    if (tid < 64) sbias2[tid] = __floats2half2_rn(b2[2 * tid], b2[2 * tid + 1]);

    if (tid == 0) {
#pragma unroll
        for (int i = 0; i < 5; i++) MBAR_INIT(sb + C2_MBAR + i * 8, 1);
    }
    __syncthreads();
    if (tid == 0) {
        MBAR_EXPECT(sb + C2_MBAR + 32, 25952);
        BULK_LD(sb + C2_HALO, (const char*)g_a1 + (size_t)n * 46720 + hf * 20736,
                25952, sb + C2_MBAR + 32);
        MBAR_EXPECT(sb + C2_MBAR + 0, C2_BSZ);
        BULK_LD(sb + C2_B0, (const char*)g_w2s, C2_BSZ, sb + C2_MBAR + 0);
        MBAR_EXPECT(sb + C2_MBAR + 8, C2_BSZ);
        BULK_LD(sb + C2_B0 + C2_BSZ, (const char*)g_w2s + C2_BSZ, C2_BSZ, sb + C2_MBAR + 8);
    }

    int y_m[2], x_m[2];
#pragma unroll
    for (int h = 0; h < 2; h++) {
        int m = (wm + 4 * h) * 16 + (lane & 15);
        int b = m >> 2, c = m & 3;
        y_m[h] = ((b >> 3) << 1) + (c >> 1);
        x_m[h] = ((b & 7) << 1) + (c & 1);
    }
    uint32_t khalf16 = (uint32_t)((lane >> 4) << 4);
    uint32_t bRowOff = (uint32_t)(wn * 64 + (lane & 15)) * 144 + khalf16;

    float acc[2][8][4];
#pragma unroll
    for (int h = 0; h < 2; h++)
#pragma unroll
        for (int i = 0; i < 8; i++)
#pragma unroll
            for (int j = 0; j < 4; j++) acc[h][i][j] = 0.f;

    MBAR_WAIT(sb + C2_MBAR + 32, 0);

    for (int tap = 0; tap < 9; tap++) {
        if (tid == 0 && tap + 2 < 9) {
            int nx = tap + 2;
            MBAR_EXPECT(sb + C2_MBAR + (nx & 3) * 8, C2_BSZ);
            BULK_LD(sb + C2_B0 + (nx & 3) * C2_BSZ, (const char*)g_w2s + nx * C2_BSZ,
                    C2_BSZ, sb + C2_MBAR + (nx & 3) * 8);
        }
        MBAR_WAIT(sb + C2_MBAR + (tap & 3) * 8, (tap >> 2) & 1);

        int ky = tap / 3, kx = tap - ky * 3;
        uint32_t aA[2];
#pragma unroll
        for (int h = 0; h < 2; h++) {
            int hy = y_m[h] + ky;
            aA[h] = sb + C2_HALO + (uint32_t)(hy * 18 + x_m[h] + kx) * 144 +
                    (uint32_t)((hy & 1) << 5) + khalf16;
        }
        uint32_t bBuf = sb + C2_B0 + (uint32_t)((tap & 3) * C2_BSZ);
#pragma unroll
        for (int kc = 0; kc < 4; kc++) {
            uint32_t a00, a01, a02, a03, a10, a11, a12, a13;
            ldsm4(aA[0] + kc * 32, a00, a01, a02, a03);
            ldsm4(aA[1] + kc * 32, a10, a11, a12, a13);
#pragma unroll
            for (int nt2 = 0; nt2 < 4; nt2++) {
                uint32_t r0, r1, r2, r3;
                ldsm4(bBuf + bRowOff + nt2 * 2304 + kc * 32, r0, r1, r2, r3);
                mmaf16(acc[0][2 * nt2],     a00, a01, a02, a03, r0, r2);
                mmaf16(acc[0][2 * nt2 + 1], a00, a01, a02, a03, r1, r3);
                mmaf16(acc[1][2 * nt2],     a10, a11, a12, a13, r0, r2);
                mmaf16(acc[1][2 * nt2 + 1], a10, a11, a12, a13, r1, r3);
            }
        }
        // ring depth 4, lookahead 2: a 2-tap sync epoch bounds warp skew so the
        // writer (buffer (T+3)&3 at worst) never collides with the slowest
        // reader (buffer T&3) — sync only after odd taps.
        if (tap & 1) __syncthreads();
    }

    float alpha = g_alpha[1];
    __half2 z2 = __floats2half2_rn(0.f, 0.f);
    int t2 = lane & 3;
    bool wr = (lane & 12) == 0;
#pragma unroll
    for (int h = 0; h < 2; h++) {
        int mt = hf * 8 + wm + 4 * h;
        int blk0 = mt * 4 + (lane >> 4);
#pragma unroll
        for (int nt = 0; nt < 8; nt++) {
            __half2 p01 = __floats2half2_rn(alpha * acc[h][nt][0], alpha * acc[h][nt][1]);
            __half2 p23 = __floats2half2_rn(alpha * acc[h][nt][2], alpha * acc[h][nt][3]);
            p01 = poolmax2(p01);
            p23 = poolmax2(p23);
            if (wr) {
                int oc = wn * 64 + nt * 8 + t2 * 2;
                __half2 bi = sbias2[oc >> 1];
                p01 = __hmax2(__hadd2(p01, bi), z2);
                p23 = __hmax2(__hadd2(p23, bi), z2);
#pragma unroll
                for (int p = 0; p < 2; p++) {
                    int blk = blk0 + p * 2;
                    int py = blk >> 3, px = blk & 7;
                    int pl = (py + 1) * 10 + (px + 1);
                    *(__half2*)((unsigned short*)g_a2 + n * A2R + pl * 136 +
                                (((py + 1) & 1) << 4) + oc) = p ? p23 : p01;
                }
            }
        }
    }
}

// ========================= conv3: 2 images x 128 oc per CTA ================
#define C3_HALO 0
#define C3_B0 54528
#define C3_BSZ 18432
#define C3_BIAS (C3_B0 + 2 * C3_BSZ)
#define C3_MBAR (C3_BIAS + 1024)
#define C3_SMEM (C3_MBAR + 32)
__global__ __launch_bounds__(256, 2) void k_conv3f(const float* __restrict__ b3) {
    extern __shared__ __align__(128) char smem[];
    uint32_t sb = smem_u32(smem);
    int tid = threadIdx.x, wid = tid >> 5, lane = tid & 31;
    int wm = wid & 3, wn = wid >> 2;
    int pr = blockIdx.x >> 1, oh = blockIdx.x & 1;
    int n0 = pr * 2;
    __half2* sbias2 = (__half2*)(smem + C3_BIAS);
    if (tid < 128) sbias2[tid] = __floats2half2_rn(b3[2 * tid], b3[2 * tid + 1]);

    if (tid == 0) {
#pragma unroll
        for (int i = 0; i < 3; i++) MBAR_INIT(sb + C3_MBAR + i * 8, 1);
    }
    __syncthreads();
    if (tid == 0) {
        MBAR_EXPECT(sb + C3_MBAR + 16, 2 * 27264);
        BULK_LD(sb + C3_HALO,         (const char*)g_a2 + (size_t)n0 * 27264,       27264, sb + C3_MBAR + 16);
        BULK_LD(sb + C3_HALO + 27264, (const char*)g_a2 + (size_t)(n0 + 1) * 27264, 27264, sb + C3_MBAR + 16);
        MBAR_EXPECT(sb + C3_MBAR + 0, C3_BSZ);
        BULK_LD(sb + C3_B0, (const char*)g_w3s + (size_t)(oh * 128) * 144, C3_BSZ, sb + C3_MBAR + 0);
    }

    int y_m[2], x_m[2], img_m[2];
#pragma unroll
    for (int h = 0; h < 2; h++) {
        int m = (wm + 4 * h) * 16 + (lane & 15);
        img_m[h] = m >> 6;
        int r = m & 63;
        int bl = r >> 2, c = r & 3;
        y_m[h] = ((bl >> 2) << 1) + (c >> 1);
        x_m[h] = ((bl & 3) << 1) + (c & 1);
    }
    uint32_t khalf16 = (uint32_t)((lane >> 4) << 4);
    uint32_t bRowOff = (uint32_t)(wn * 64 + (lane & 15)) * 144 + khalf16;

    float acc[2][8][4];
#pragma unroll
    for (int h = 0; h < 2; h++)
#pragma unroll
        for (int i = 0; i < 8; i++)
#pragma unroll
            for (int j = 0; j < 4; j++) acc[h][i][j] = 0.f;

    MBAR_WAIT(sb + C3_MBAR + 16, 0);

    for (int st = 0; st < 18; st++) {
        if (tid == 0 && st + 1 < 18) {
            int nx = st + 1;
            MBAR_EXPECT(sb + C3_MBAR + (nx & 1) * 8, C3_BSZ);
            BULK_LD(sb + C3_B0 + (nx & 1) * C3_BSZ,
                    (const char*)g_w3s + (size_t)(nx * 256 + oh * 128) * 144,
                    C3_BSZ, sb + C3_MBAR + (nx & 1) * 8);
        }
        MBAR_WAIT(sb + C3_MBAR + (st & 1) * 8, (st >> 1) & 1);

        int tap = st >> 1, chalf = (st & 1) * 128;
        int ky = tap / 3, kx = tap - ky * 3;
        uint32_t aA[2];
#pragma unroll
        for (int h = 0; h < 2; h++) {
            int hy = y_m[h] + ky;
            aA[h] = sb + C3_HALO + (uint32_t)(img_m[h] * 27264) +
                    (uint32_t)(hy * 10 + x_m[h] + kx) * 272 +
                    (uint32_t)((hy & 1) << 5) + (uint32_t)chalf + khalf16;
        }
        uint32_t bBuf = sb + C3_B0 + (uint32_t)((st & 1) * C3_BSZ);
#pragma unroll
        for (int kc = 0; kc < 4; kc++) {
            uint32_t a00, a01, a02, a03, a10, a11, a12, a13;
            ldsm4(aA[0] + kc * 32, a00, a01, a02, a03);
            ldsm4(aA[1] + kc * 32, a10, a11, a12, a13);
#pragma unroll
            for (int nt2 = 0; nt2 < 4; nt2++) {
                uint32_t r0, r1, r2, r3;
                ldsm4(bBuf + bRowOff + nt2 * 2304 + kc * 32, r0, r1, r2, r3);
                mmaf16(acc[0][2 * nt2],     a00, a01, a02, a03, r0, r2);
                mmaf16(acc[0][2 * nt2 + 1], a00, a01, a02, a03, r1, r3);
                mmaf16(acc[1][2 * nt2],     a10, a11, a12, a13, r0, r2);
                mmaf16(acc[1][2 * nt2 + 1], a10, a11, a12, a13, r1, r3);
            }
        }
        __syncthreads();   // 2-deep ring, 1-stage lookahead: per-stage sync required
    }

    float alpha = g_alpha[2];
    __half2 z2 = __floats2half2_rn(0.f, 0.f);
    int t2 = lane & 3;
    bool wr = (lane & 12) == 0;
#pragma unroll
    for (int h = 0; h < 2; h++) {
        int mt = wm + 4 * h;
        int img = n0 + (mt >> 2);
        int blk0 = (mt & 3) * 4 + (lane >> 4);
#pragma unroll
        for (int nt = 0; nt < 8; nt++) {
            __half2 p01 = __floats2half2_rn(alpha * acc[h][nt][0], alpha * acc[h][nt][1]);
            __half2 p23 = __floats2half2_rn(alpha * acc[h][nt][2], alpha * acc[h][nt][3]);
            p01 = poolmax2(p01);
            p23 = poolmax2(p23);
            if (wr) {
                int oc = oh * 128 + wn * 64 + nt * 8 + t2 * 2;
                __half2 bi = sbias2[oc >> 1];
                p01 = __hmax2(__hadd2(p01, bi), z2);
                p23 = __hmax2(__hadd2(p23, bi), z2);
#pragma unroll
                for (int p = 0; p < 2; p++) {
                    int blk = blk0 + p * 2;
                    *(__half2*)((unsigned short*)g_act3 + (img * 16 + blk) * 256 + oc) =
                        p ? p23 : p01;
                }
            }
        }
    }
}

// ========================= fc1 (split-K 16) =================================
#define F1_SA 0
#define F1_SB 18432
#define F1_SMEM 36880
__global__ __launch_bounds__(256, 2) void k_fc1f() {
    extern __shared__ __align__(128) char smem[];
    uint32_t sbase = smem_u32(smem);
    int tid = threadIdx.x, wid = tid >> 5, lane = tid & 31;
    int m0 = blockIdx.x * 128, o0 = blockIdx.y * 128, k0 = blockIdx.z * 256;

    int row = tid >> 1, half = tid & 1;

    float acc[16][4];
#pragma unroll
    for (int i = 0; i < 16; i++)
#pragma unroll
        for (int j = 0; j < 4; j++) acc[i][j] = 0.f;

    int arow_l = wid * 16 + (lane & 15);
    uint32_t khalf16 = (uint32_t)((lane >> 4) << 4);
    uint32_t aAddr = sbase + F1_SA + (uint32_t)arow_l * 144 + khalf16;
    uint32_t bAddr0 = sbase + F1_SB + (uint32_t)(lane & 15) * 144 + khalf16;

    for (int st = 0; st < 4; st++) {
        int koff = k0 + st * 64;
        __syncthreads();
        {
            const h16* srcA = g_act3 + (m0 + row) * 4096 + koff + half * 32;
            const h16* srcB = g_wf1s + (o0 + row) * 4096 + koff + half * 32;
            char* dA = smem + F1_SA + row * 144 + half * 64;
            char* dB = smem + F1_SB + row * 144 + half * 64;
#pragma unroll
            for (int j = 0; j < 4; j++) {
                *(uint4*)(dA + j * 16) = *(const uint4*)(srcA + j * 8);
                *(uint4*)(dB + j * 16) = *(const uint4*)(srcB + j * 8);
            }
        }
        __syncthreads();
#pragma unroll
        for (int kc = 0; kc < 4; kc++) {
            uint32_t kofs = (uint32_t)(kc * 32);
            uint32_t a0, a1, a2, a3;
            ldsm4(aAddr + kofs, a0, a1, a2, a3);
#pragma unroll
            for (int nt2 = 0; nt2 < 8; nt2++) {
                uint32_t r0, r1, r2, r3;
                ldsm4(bAddr0 + kofs + nt2 * 2304, r0, r1, r2, r3);
                mmaf16(acc[2 * nt2],     a0, a1, a2, a3, r0, r2);
                mmaf16(acc[2 * nt2 + 1], a0, a1, a2, a3, r1, r3);
            }
        }
    }

    float* dst = g_fc1p + (long)blockIdx.z * (NB * 256);
    int g = lane >> 2, t2 = lane & 3;
    int orow = m0 + wid * 16 + g;
#pragma unroll
    for (int nt = 0; nt < 16; nt++) {
        int col = o0 + nt * 8 + t2 * 2;
        float2 p0; p0.x = acc[nt][0]; p0.y = acc[nt][1];
        float2 p1; p1.x = acc[nt][2]; p1.y = acc[nt][3];
        *(float2*)(dst + orow * 256 + col) = p0;
        *(float2*)(dst + (orow + 8) * 256 + col) = p1;
    }
}

// ========================= fc1red + fc2 fused (320 thr = 10 warps) ==========
__global__ void k_fcout(const float* __restrict__ bf1, const float* __restrict__ bf2,
                        float* __restrict__ out) {
    __shared__ float a[256];
    int n = blockIdx.x, tid = threadIdx.x;
    float al3 = g_alpha[3], al4 = g_alpha[4];
    if (tid < 256) {
        float v = 0.f;
#pragma unroll
        for (int s = 0; s < 16; s++) v += g_fc1p[(long)s * NB * 256 + n * 256 + tid];
        a[tid] = fmaxf(al3 * v + bf1[tid], 0.f);
    }
    __syncthreads();
    int w = tid >> 5, l = tid & 31;
    const float* wr = &g_wf2t[w * 256];
    float s = 0.f;
#pragma unroll
    for (int k = 0; k < 8; k++) s += a[l + 32 * k] * wr[l + 32 * k];
#pragma unroll
    for (int off = 16; off; off >>= 1) s += __shfl_xor_sync(0xffffffffu, s, off);
    if (l == 0) out[n * 10 + w] = al4 * s + bf2[w];
}

// ========================= launch ===========================================
extern "C" void kernel_launch(void* const* d_in, const int* in_sizes, int n_in,
                              void* d_out, int out_size) {
    const float* x   = (const float*)d_in[0];
    const float* w1  = (const float*)d_in[1];
    const float* b1  = (const float*)d_in[2];
    const float* w2  = (const float*)d_in[3];
    const float* b2  = (const float*)d_in[4];
    const float* w3  = (const float*)d_in[5];
    const float* b3  = (const float*)d_in[6];
    const float* wf1 = (const float*)d_in[7];
    const float* bf1 = (const float*)d_in[8];
    const float* wf2 = (const float*)d_in[9];
    const float* bf2 = (const float*)d_in[10];
    float* out = (float*)d_out;

    static int configured = 0;
    if (!configured) {
        cudaFuncSetAttribute(k_conv1t, cudaFuncAttributeMaxDynamicSharedMemorySize, C1_SMEM);
        cudaFuncSetAttribute(k_conv2f, cudaFuncAttributeMaxDynamicSharedMemorySize, C2_SMEM);
        cudaFuncSetAttribute(k_conv3f, cudaFuncAttributeMaxDynamicSharedMemorySize, C3_SMEM);
        cudaFuncSetAttribute(k_fc1f,   cudaFuncAttributeMaxDynamicSharedMemorySize, F1_SMEM);
        configured = 1;
    }

    k_tern1<<<dim3(128, 5), 256>>>(w1, w2, w3, wf1, wf2);
    k_tern2<<<dim3(256, 5), 256>>>(w1, w2, w3, wf1, wf2);
    k_conv1t<<<NB * 4, 256, C1_SMEM>>>(x, b1);
    k_conv2f<<<NB * 2, 256, C2_SMEM>>>(b2);
    k_conv3f<<<NB, 256, C3_SMEM>>>(b3);
    k_fc1f<<<dim3(8, 2, 16), 256, F1_SMEM>>>();
    k_fcout<<<NB, 320>>>(bf1, bf2, out);
}